// round 15
// baseline (speedup 1.0000x reference)
#include <cuda_runtime.h>
#include <cuda_bf16.h>
#include <math.h>
#include <stdint.h>

#define NN 200000
#define EE 1600000
#define GG 1024
#define HH 256
#define FF 7

// ---------------- scratch (device globals, no allocation) ----------------
static __device__ __nv_bfloat16 g_HA[(size_t)NN*HH];
static __device__ __nv_bfloat16 g_LA[(size_t)NN*HH];
static __device__ __nv_bfloat16 g_HB[(size_t)NN*HH];
static __device__ __nv_bfloat16 g_LB[(size_t)NN*HH];
static __device__ __nv_bfloat16 g_HC[(size_t)NN*HH];
static __device__ __nv_bfloat16 g_LC[(size_t)NN*HH];
static __device__ __nv_bfloat16 g_HD[(size_t)NN*HH];
static __device__ __nv_bfloat16 g_LD[(size_t)NN*HH];
static __device__ float g_F[(size_t)NN*HH];
static __device__ float g_asrc[NN*4];
static __device__ float g_adst[NN*4];
static __device__ float g_dinv[NN];
static __device__ int   g_degi[NN];
static __device__ int   g_rowptr[NN+1];
static __device__ int   g_fillc[NN];
static __device__ int   g_csr[EE];
static __device__ int   g_bsum[256];
static __device__ float g_xp[GG*2*HH];
static __device__ float g_z1[GG*HH];
static __device__ __nv_bfloat16 g_Whi[7*65536];
static __device__ __nv_bfloat16 g_Wlo[7*65536];

__device__ __forceinline__ float gelu_exact(float v) {
    return 0.5f * v * (1.0f + erff(v * 0.7071067811865476f));
}

// ================= warp-MMA helpers (sm_80+ baseline PTX) =================
__device__ __forceinline__ uint32_t smem_u32(const void* p) {
    uint32_t a;
    asm("{ .reg .u64 t; cvta.to.shared.u64 t, %1; cvt.u32.u64 %0, t; }"
        : "=r"(a) : "l"(p));
    return a;
}
__device__ __forceinline__ void mma16816(float* c, const uint32_t* a, const uint32_t* b) {
    asm volatile("mma.sync.aligned.m16n8k16.row.col.f32.bf16.bf16.f32 "
        "{%0,%1,%2,%3}, {%4,%5,%6,%7}, {%8,%9}, {%0,%1,%2,%3};"
        : "+f"(c[0]), "+f"(c[1]), "+f"(c[2]), "+f"(c[3])
        : "r"(a[0]), "r"(a[1]), "r"(a[2]), "r"(a[3]), "r"(b[0]), "r"(b[1]));
}
__device__ __forceinline__ void ldm4(uint32_t* r, uint32_t addr) {
    asm volatile("ldmatrix.sync.aligned.m8n8.x4.shared.b16 {%0,%1,%2,%3}, [%4];"
        : "=r"(r[0]), "=r"(r[1]), "=r"(r[2]), "=r"(r[3]) : "r"(addr));
}
__device__ __forceinline__ void cpasync16(uint32_t dst, const void* src) {
    asm volatile("cp.async.cg.shared.global [%0], [%1], 16;" :: "r"(dst), "l"(src));
}
__device__ __forceinline__ void cpasync16z(uint32_t dst, const void* src, int n) {
    asm volatile("cp.async.cg.shared.global [%0], [%1], 16, %2;"
                 :: "r"(dst), "l"(src), "r"(n));
}
#define CP_COMMIT() asm volatile("cp.async.commit_group;" ::: "memory")
#define CP_WAIT1()  asm volatile("cp.async.wait_group 1;" ::: "memory")
#define CP_WAIT0()  asm volatile("cp.async.wait_group 0;" ::: "memory")

__device__ __forceinline__ uint32_t swz(int row, int kg) {
    return (uint32_t)(row * 64 + ((kg ^ ((row >> 1) & 3)) << 4));
}
__device__ __forceinline__ uint32_t pack_hilo(float a, float b, uint32_t& lo) {
    __nv_bfloat16 ha = __float2bfloat16_rn(a), hb = __float2bfloat16_rn(b);
    __nv_bfloat162 l2 = __floats2bfloat162_rn(a - __bfloat162float(ha),
                                              b - __bfloat162float(hb));
    __nv_bfloat162 h2(ha, hb);
    lo = *(uint32_t*)&l2;
    return *(uint32_t*)&h2;
}
__device__ __forceinline__ void unpack8(const uint4 H, const uint4 L, float* v) {
    const __nv_bfloat162* hp = (const __nv_bfloat162*)&H;
    const __nv_bfloat162* lp = (const __nv_bfloat162*)&L;
#pragma unroll
    for (int i = 0; i < 4; i++) {
        float2 a = __bfloat1622float2(hp[i]);
        float2 b = __bfloat1622float2(lp[i]);
        v[2*i]   = a.x + b.x;
        v[2*i+1] = a.y + b.y;
    }
}

// stage: AHI[0,8K) ALO[8K,16K) BHI[16K,24K) BLO[24K,32K); 3 stages
#define STG 32768
#define SMTOT (3*STG)

// ------------- weight transpose + bf16 hi/lo split (all 7 in one) --------
__global__ void k_wsplit7(const float* __restrict__ gat_w, const float* __restrict__ tag_ws,
                          const float* __restrict__ gc_w_rel, const float* __restrict__ gc_w_root,
                          __nv_bfloat16* __restrict__ hi, __nv_bfloat16* __restrict__ lo) {
    int slot = blockIdx.y;
    const float* W = (slot == 0) ? gat_w
                   : (slot <= 4) ? tag_ws + (size_t)(slot-1)*65536
                   : (slot == 5) ? gc_w_rel : gc_w_root;
    int idx = blockIdx.x * blockDim.x + threadIdx.x;
    if (idx >= 65536) return;
    int k = idx >> 8, n = idx & 255;
    float v = W[idx];
    __nv_bfloat16 h = __float2bfloat16_rn(v);
    float r = v - __bfloat162float(h);
    hi[(size_t)slot*65536 + n*256 + k] = h;
    lo[(size_t)slot*65536 + n*256 + k] = __float2bfloat16_rn(r);
}

// ---- tensor-core mega-GEMM, exact 3-product, 3-stage cp.async, 2 CTA/SM --
// grid = (2, M-tiles): x = N-half (fastest) so both N-halves of one M tile
// are adjacent in launch order and share A rows through L2.
__global__ void __launch_bounds__(256, 2)
k_gemm_mma(const __nv_bfloat16* H0, const __nv_bfloat16* L0,
           const __nv_bfloat16* H1, const __nv_bfloat16* L1,
           const __nv_bfloat16* H2, const __nv_bfloat16* L2,
           const __nv_bfloat16* H3, const __nv_bfloat16* L3,
           const __nv_bfloat16* __restrict__ Whi, const __nv_bfloat16* __restrict__ Wlo,
           int w0, int w1, int w2, int w3, int ninputs,
           float* outf, __nv_bfloat16* outh, __nv_bfloat16* outl,
           const float* bias, int relu) {
    extern __shared__ char sm[];
    uint32_t sb = smem_u32(sm);
    const int t = threadIdx.x;
    const int m0 = blockIdx.y * 128;
    const int n0 = blockIdx.x * 128;
    const __nv_bfloat16* His[4] = {H0, H1, H2, H3};
    const __nv_bfloat16* Lis[4] = {L0, L1, L2, L3};
    const int wof[4] = {w0, w1, w2, w3};
    const int CHN = ninputs * 8;

    const int r  = t >> 1;
    const int hf = t & 1;
    const int am = m0 + r;
    const int av = (am < NN) ? 16 : 0;
    const uint32_t s0 = swz(r, hf*2), s1 = swz(r, hf*2 + 1);

    float acc[2][8][4];
#pragma unroll
    for (int i = 0; i < 2; i++)
#pragma unroll
        for (int j = 0; j < 8; j++)
#pragma unroll
            for (int q = 0; q < 4; q++) acc[i][j][q] = 0.0f;

    auto issue = [&](int c, int stg) {
        int i = c >> 3, kc = c & 7;
        uint32_t base = sb + stg * STG;
        size_t aoff = (size_t)am * 256 + kc * 32 + hf * 16;
        size_t boff = (size_t)wof[i] * 65536 + (size_t)(n0 + r) * 256 + kc * 32 + hf * 16;
        cpasync16z(base + s0,         His[i] + aoff,     av);
        cpasync16z(base + s1,         His[i] + aoff + 8, av);
        cpasync16z(base + 8192 + s0,  Lis[i] + aoff,     av);
        cpasync16z(base + 8192 + s1,  Lis[i] + aoff + 8, av);
        cpasync16 (base + 16384 + s0, Whi + boff);
        cpasync16 (base + 16384 + s1, Whi + boff + 8);
        cpasync16 (base + 24576 + s0, Wlo + boff);
        cpasync16 (base + 24576 + s1, Wlo + boff + 8);
    };

    issue(0, 0); CP_COMMIT();
    if (CHN > 1) { issue(1, 1); CP_COMMIT(); }

    const int lane = t & 31, wid = t >> 5;
    const int wm = wid & 3, wn = wid >> 2;

    for (int c = 0; c < CHN; c++) {
        if (c + 1 < CHN) CP_WAIT1(); else CP_WAIT0();
        __syncthreads();
        if (c + 2 < CHN) { issue(c + 2, (c + 2) % 3); CP_COMMIT(); }

        uint32_t ab = sb + (c % 3) * STG;
        uint32_t alb = ab + 8192, bb = ab + 16384, blb = ab + 24576;
#pragma unroll
        for (int ks = 0; ks < 2; ks++) {
            uint32_t ah[2][4], al[2][4];
#pragma unroll
            for (int mf = 0; mf < 2; mf++) {
                int row = wm*32 + mf*16 + (lane & 15);
                int kg = ks*2 + (lane >> 4);
                ldm4(ah[mf], ab  + swz(row, kg));
                ldm4(al[mf], alb + swz(row, kg));
            }
#pragma unroll
            for (int nf2 = 0; nf2 < 4; nf2++) {
                int nrow = wn*64 + nf2*16 + (lane & 7) + ((lane >> 4) << 3);
                int kg = ks*2 + ((lane >> 3) & 1);
                uint32_t bh[4], bl[4];
                ldm4(bh, bb  + swz(nrow, kg));
                ldm4(bl, blb + swz(nrow, kg));
#pragma unroll
                for (int mf = 0; mf < 2; mf++) {
#pragma unroll
                    for (int h = 0; h < 2; h++) {
                        float* a = acc[mf][nf2*2 + h];
                        mma16816(a, ah[mf], bh + h*2);
                        mma16816(a, ah[mf], bl + h*2);
                        mma16816(a, al[mf], bh + h*2);
                    }
                }
            }
        }
    }

    const int mb = m0 + wm*32;
    const int nb = n0 + wn*64;
#pragma unroll
    for (int mf = 0; mf < 2; mf++) {
        int r0 = mb + mf*16 + (lane >> 2);
        int r1 = r0 + 8;
#pragma unroll
        for (int nf = 0; nf < 8; nf++) {
            int col = nb + nf*8 + (lane & 3)*2;
            float a0 = acc[mf][nf][0], a1 = acc[mf][nf][1];
            float a2 = acc[mf][nf][2], a3 = acc[mf][nf][3];
            if (outf) {
                float b0 = 0.f, b1 = 0.f;
                if (bias) { b0 = bias[col]; b1 = bias[col+1]; }
                float2 v0 = make_float2(a0 + b0, a1 + b1);
                float2 v1 = make_float2(a2 + b0, a3 + b1);
                if (relu) {
                    v0.x = fmaxf(v0.x, 0.f); v0.y = fmaxf(v0.y, 0.f);
                    v1.x = fmaxf(v1.x, 0.f); v1.y = fmaxf(v1.y, 0.f);
                }
                if (r0 < NN) *(float2*)(outf + (size_t)r0*256 + col) = v0;
                if (r1 < NN) *(float2*)(outf + (size_t)r1*256 + col) = v1;
            } else {
                uint32_t l0, l1;
                uint32_t h0 = pack_hilo(a0, a1, l0);
                uint32_t h1 = pack_hilo(a2, a3, l1);
                if (r0 < NN) {
                    *(uint32_t*)(outh + (size_t)r0*256 + col) = h0;
                    *(uint32_t*)(outl + (size_t)r0*256 + col) = l0;
                }
                if (r1 < NN) {
                    *(uint32_t*)(outh + (size_t)r1*256 + col) = h1;
                    *(uint32_t*)(outl + (size_t)r1*256 + col) = l1;
                }
            }
        }
    }
}

// ================= CSR construction (counting sort by dst) ================
__global__ void k_degi(const int* __restrict__ ei, int* __restrict__ degi) {
    int e = blockIdx.x * blockDim.x + threadIdx.x;
    if (e >= EE) return;
    atomicAdd(&degi[ei[EE + e]], 1);
}

__global__ void k_scan1(const int* __restrict__ degi, int* __restrict__ bsum) {
    __shared__ int s[256];
    int t = threadIdx.x, b = blockIdx.x;
    int base = b*1024 + t*4;
    int sum = 0;
#pragma unroll
    for (int k = 0; k < 4; k++) { int i = base + k; if (i < NN) sum += degi[i]; }
    s[t] = sum; __syncthreads();
    for (int off = 128; off > 0; off >>= 1) {
        if (t < off) s[t] += s[t+off];
        __syncthreads();
    }
    if (t == 0) bsum[b] = s[0];
}

__global__ void k_scan2(int* __restrict__ bsum, int* __restrict__ rowptr, int nblk) {
    if (threadIdx.x == 0 && blockIdx.x == 0) {
        int run = 0;
        for (int i = 0; i < nblk; i++) { int v = bsum[i]; bsum[i] = run; run += v; }
        rowptr[NN] = run;
    }
}

__global__ void k_scan3(const int* __restrict__ degi, const int* __restrict__ bsum,
                        int* __restrict__ rowptr) {
    __shared__ int s[256];
    int t = threadIdx.x, b = blockIdx.x;
    int base = b*1024 + t*4;
    int v[4]; int sum = 0;
#pragma unroll
    for (int k = 0; k < 4; k++) { int i = base + k; v[k] = (i < NN) ? degi[i] : 0; sum += v[k]; }
    s[t] = sum; __syncthreads();
    for (int off = 1; off < 256; off <<= 1) {
        int u = (t >= off) ? s[t-off] : 0;
        __syncthreads();
        s[t] += u;
        __syncthreads();
    }
    int run = bsum[b] + s[t] - sum;
#pragma unroll
    for (int k = 0; k < 4; k++) {
        int i = base + k;
        if (i < NN) rowptr[i] = run;
        run += v[k];
    }
}

__global__ void k_csrfill(const int* __restrict__ ei, const int* __restrict__ rowptr,
                          int* __restrict__ fillc, int* __restrict__ csr) {
    int e = blockIdx.x * blockDim.x + threadIdx.x;
    if (e >= EE) return;
    int r = ei[e], c = ei[EE + e];
    int pos = rowptr[c] + atomicAdd(&fillc[c], 1);
    csr[pos] = r;
}

__global__ void k_dinv2(const int* __restrict__ degi, float* __restrict__ dinv) {
    int i = blockIdx.x * blockDim.x + threadIdx.x;
    if (i >= NN) return;
    int d = degi[i];
    dinv[i] = d > 0 ? 1.0f / sqrtf((float)d) : 0.0f;
}

// ------------- encoder: h = gelu(x @ enc_w + enc_b) -> hi/lo -------------
__global__ void k_encoder(const float* __restrict__ x, const float* __restrict__ w,
                          const float* __restrict__ b,
                          __nv_bfloat16* __restrict__ Hd, __nv_bfloat16* __restrict__ Ld) {
    int idx = blockIdx.x * blockDim.x + threadIdx.x;
    if (idx >= NN * HH) return;
    int n = idx >> 8, j = idx & 255;
    float s = b[j];
#pragma unroll
    for (int f = 0; f < FF; f++) s += x[n*FF + f] * w[f*HH + j];
    float v = gelu_exact(s);
    __nv_bfloat16 h = __float2bfloat16_rn(v);
    Hd[idx] = h;
    Ld[idx] = __float2bfloat16_rn(v - __bfloat162float(h));
}

// ---------------- GAT attention scores (hi/lo input) ----------------
__global__ void k_attn(const __nv_bfloat16* __restrict__ Hh, const __nv_bfloat16* __restrict__ Lh,
                       const float* __restrict__ att_src, const float* __restrict__ att_dst,
                       float* __restrict__ asrc, float* __restrict__ adst) {
    int idx = blockIdx.x * blockDim.x + threadIdx.x;
    if (idx >= NN * 4) return;
    int n = idx >> 2, h = idx & 3;
    const uint4* hb = (const uint4*)(Hh + (size_t)n * HH + h * 64);
    const uint4* lb = (const uint4*)(Lh + (size_t)n * HH + h * 64);
    const float* ws = att_src + h * 64;
    const float* wd = att_dst + h * 64;
    float s = 0.f, d = 0.f;
#pragma unroll
    for (int i = 0; i < 8; i++) {
        float v[8];
        unpack8(hb[i], lb[i], v);
#pragma unroll
        for (int q = 0; q < 8; q++) {
            float wv = ws[i*8 + q], dv = wd[i*8 + q];
            s += v[q] * wv;
            d += v[q] * dv;
        }
    }
    asrc[idx] = s; adst[idx] = d;
}

__device__ __forceinline__ float4 lrelu4(float4 v) {
    v.x = v.x > 0.f ? v.x : 0.2f*v.x;
    v.y = v.y > 0.f ? v.y : 0.2f*v.y;
    v.z = v.z > 0.f ? v.z : 0.2f*v.z;
    v.w = v.w > 0.f ? v.w : 0.2f*v.w;
    return v;
}

// ------- GAT: warp-per-dst softmax + weighted gather (hi/lo in, fp32 out) --
__global__ void __launch_bounds__(256)
k_gat(const int* __restrict__ rowptr, const int* __restrict__ csr,
      const float* __restrict__ asrc, const float* __restrict__ adst,
      const __nv_bfloat16* __restrict__ Hh, const __nv_bfloat16* __restrict__ Lh,
      float* __restrict__ out) {
    __shared__ int   s_sh[8][32];
    __shared__ float4 al_sh[8][32];
    int w = (blockIdx.x * blockDim.x + threadIdx.x) >> 5;
    if (w >= NN) return;
    int lane = threadIdx.x & 31;
    int wid = (threadIdx.x >> 5);
    int r0 = rowptr[w], deg = rowptr[w+1] - r0;
    int tot = deg + 1;
    float4 ad = *(const float4*)(adst + (size_t)w*4);
    int head = lane >> 3;
    float acc[8];
#pragma unroll
    for (int q = 0; q < 8; q++) acc[q] = 0.f;

    for (int base = 0; base < tot; base += 32) {
        int j = base + lane;
        int s = w;
        float4 al = make_float4(0.f, 0.f, 0.f, 0.f);
        bool valid = j < tot;
        float4 e = make_float4(-3.4e38f, -3.4e38f, -3.4e38f, -3.4e38f);
        if (valid) {
            if (j < deg) s = csr[r0 + j];
            float4 as = *(const float4*)(asrc + (size_t)s*4);
            e = lrelu4(make_float4(as.x+ad.x, as.y+ad.y, as.z+ad.z, as.w+ad.w));
        }
        float4 mx, den;
        if (tot <= 32) {
            mx = e;
#pragma unroll
            for (int off = 16; off > 0; off >>= 1) {
                mx.x = fmaxf(mx.x, __shfl_xor_sync(~0u, mx.x, off));
                mx.y = fmaxf(mx.y, __shfl_xor_sync(~0u, mx.y, off));
                mx.z = fmaxf(mx.z, __shfl_xor_sync(~0u, mx.z, off));
                mx.w = fmaxf(mx.w, __shfl_xor_sync(~0u, mx.w, off));
            }
            den = make_float4(valid ? expf(e.x - mx.x) : 0.f,
                              valid ? expf(e.y - mx.y) : 0.f,
                              valid ? expf(e.z - mx.z) : 0.f,
                              valid ? expf(e.w - mx.w) : 0.f);
            float4 ex = den;
#pragma unroll
            for (int off = 16; off > 0; off >>= 1) {
                den.x += __shfl_xor_sync(~0u, den.x, off);
                den.y += __shfl_xor_sync(~0u, den.y, off);
                den.z += __shfl_xor_sync(~0u, den.z, off);
                den.w += __shfl_xor_sync(~0u, den.w, off);
            }
            al = make_float4(ex.x/den.x, ex.y/den.y, ex.z/den.z, ex.w/den.w);
        } else {
            mx = make_float4(-3.4e38f, -3.4e38f, -3.4e38f, -3.4e38f);
            for (int jj = lane; jj < tot; jj += 32) {
                int ss = (jj < deg) ? csr[r0 + jj] : w;
                float4 as = *(const float4*)(asrc + (size_t)ss*4);
                float4 ee = lrelu4(make_float4(as.x+ad.x, as.y+ad.y, as.z+ad.z, as.w+ad.w));
                mx.x = fmaxf(mx.x, ee.x); mx.y = fmaxf(mx.y, ee.y);
                mx.z = fmaxf(mx.z, ee.z); mx.w = fmaxf(mx.w, ee.w);
            }
#pragma unroll
            for (int off = 16; off > 0; off >>= 1) {
                mx.x = fmaxf(mx.x, __shfl_xor_sync(~0u, mx.x, off));
                mx.y = fmaxf(mx.y, __shfl_xor_sync(~0u, mx.y, off));
                mx.z = fmaxf(mx.z, __shfl_xor_sync(~0u, mx.z, off));
                mx.w = fmaxf(mx.w, __shfl_xor_sync(~0u, mx.w, off));
            }
            den = make_float4(0.f, 0.f, 0.f, 0.f);
            for (int jj = lane; jj < tot; jj += 32) {
                int ss = (jj < deg) ? csr[r0 + jj] : w;
                float4 as = *(const float4*)(asrc + (size_t)ss*4);
                float4 ee = lrelu4(make_float4(as.x+ad.x, as.y+ad.y, as.z+ad.z, as.w+ad.w));
                den.x += expf(ee.x - mx.x); den.y += expf(ee.y - mx.y);
                den.z += expf(ee.z - mx.z); den.w += expf(ee.w - mx.w);
            }
#pragma unroll
            for (int off = 16; off > 0; off >>= 1) {
                den.x += __shfl_xor_sync(~0u, den.x, off);
                den.y += __shfl_xor_sync(~0u, den.y, off);
                den.z += __shfl_xor_sync(~0u, den.z, off);
                den.w += __shfl_xor_sync(~0u, den.w, off);
            }
            if (valid) {
                al.x = expf(e.x - mx.x) / den.x;
                al.y = expf(e.y - mx.y) / den.y;
                al.z = expf(e.z - mx.z) / den.z;
                al.w = expf(e.w - mx.w) / den.w;
            }
        }
        __syncwarp();
        s_sh[wid][lane] = s;
        al_sh[wid][lane] = al;
        __syncwarp();
        int cnt = min(32, tot - base);
        for (int i = 0; i < cnt; i++) {
            int ss = s_sh[wid][i];
            float aa = ((const float*)&al_sh[wid][i])[head];
            uint4 Hv = *(const uint4*)(Hh + (size_t)ss*256 + lane*8);
            uint4 Lv = *(const uint4*)(Lh + (size_t)ss*256 + lane*8);
            float v[8];
            unpack8(Hv, Lv, v);
#pragma unroll
            for (int q = 0; q < 8; q++) acc[q] += aa * v[q];
        }
    }
    float* op = out + (size_t)w*256 + lane*8;
    *(float4*)op       = make_float4(acc[0], acc[1], acc[2], acc[3]);
    *(float4*)(op + 4) = make_float4(acc[4], acc[5], acc[6], acc[7]);
}

// ------- CSR propagation (hi/lo in, hi/lo out) ----------------------------
__global__ void __launch_bounds__(256)
k_prop_csr(const int* __restrict__ rowptr, const int* __restrict__ csr,
           const float* __restrict__ dinv,
           const __nv_bfloat16* __restrict__ Hs, const __nv_bfloat16* __restrict__ Ls,
           __nv_bfloat16* __restrict__ Hd, __nv_bfloat16* __restrict__ Ld) {
    int c = (blockIdx.x * blockDim.x + threadIdx.x) >> 5;
    if (c >= NN) return;
    int lane = threadIdx.x & 31;
    int r0 = rowptr[c], deg = rowptr[c+1] - r0;
    float nc = dinv ? dinv[c] : 1.0f;
    float acc[8];
#pragma unroll
    for (int q = 0; q < 8; q++) acc[q] = 0.f;
    for (int base = 0; base < deg; base += 32) {
        int j = base + lane;
        int s = 0; float wt = 0.f;
        if (j < deg) {
            s = csr[r0 + j];
            wt = dinv ? dinv[s] * nc : 1.0f;
        }
        int cnt = min(32, deg - base);
        for (int i = 0; i < cnt; i++) {
            int ss = __shfl_sync(~0u, s, i);
            float ww = __shfl_sync(~0u, wt, i);
            uint4 Hv = *(const uint4*)(Hs + (size_t)ss*256 + lane*8);
            uint4 Lv = *(const uint4*)(Ls + (size_t)ss*256 + lane*8);
            float v[8];
            unpack8(Hv, Lv, v);
#pragma unroll
            for (int q = 0; q < 8; q++) acc[q] += ww * v[q];
        }
    }
    uint32_t l0, l1, l2, l3;
    uint32_t h0 = pack_hilo(acc[0], acc[1], l0);
    uint32_t h1 = pack_hilo(acc[2], acc[3], l1);
    uint32_t h2 = pack_hilo(acc[4], acc[5], l2);
    uint32_t h3 = pack_hilo(acc[6], acc[7], l3);
    *(uint4*)(Hd + (size_t)c*256 + lane*8) = make_uint4(h0, h1, h2, h3);
    *(uint4*)(Ld + (size_t)c*256 + lane*8) = make_uint4(l0, l1, l2, l3);
}

// ------- graph_norm (+prebias) + relu: fp32 in, hi/lo out ------------------
__global__ void __launch_bounds__(256)
k_gnorm(const float* __restrict__ in,
        __nv_bfloat16* __restrict__ Hd, __nv_bfloat16* __restrict__ Ld,
        const float* __restrict__ pb, const float* __restrict__ w,
        const float* __restrict__ b, const float* __restrict__ ms) {
    int g = blockIdx.x, f = threadIdx.x;
    int start = (g * NN + GG - 1) / GG;
    int end = ((g + 1) * NN + GG - 1) / GG;
    float cnt = (float)(end - start);
    float pbf = pb ? pb[f] : 0.0f;
    float s1 = 0.f, s2 = 0.f;
    int n = start;
    for (; n + 4 <= end; n += 4) {
        float y0 = in[(size_t)(n+0)*HH + f] + pbf;
        float y1 = in[(size_t)(n+1)*HH + f] + pbf;
        float y2 = in[(size_t)(n+2)*HH + f] + pbf;
        float y3 = in[(size_t)(n+3)*HH + f] + pbf;
        s1 += y0 + y1 + y2 + y3;
        s2 += y0*y0 + y1*y1 + y2*y2 + y3*y3;
    }
    for (; n < end; n++) {
        float y = in[(size_t)n*HH + f] + pbf;
        s1 += y; s2 += y*y;
    }
    float mu = s1 / cnt;
    float msf = ms[f];
    float var = s2 / cnt - msf * (2.0f - msf) * mu * mu;
    float scale = rsqrtf(var + 1e-5f) * w[f];
    float bf = b[f];
    float sub = msf * mu;
    for (n = start; n < end; n++) {
        float tt = (in[(size_t)n*HH + f] + pbf - sub) * scale + bf;
        tt = fmaxf(tt, 0.0f);
        __nv_bfloat16 h = __float2bfloat16_rn(tt);
        Hd[(size_t)n*HH + f] = h;
        Ld[(size_t)n*HH + f] = __float2bfloat16_rn(tt - __bfloat162float(h));
    }
}

// ---------------- pooling: [max | mean] per graph (fp32 in) ----------------
__global__ void __launch_bounds__(256)
k_pool(const float* __restrict__ in, float* __restrict__ xp) {
    int g = blockIdx.x, f = threadIdx.x;
    int start = (g * NN + GG - 1) / GG;
    int end = ((g + 1) * NN + GG - 1) / GG;
    float cnt = (float)(end - start);
    float mx = -3.4e38f, sm = 0.f;
    int n = start;
    for (; n + 4 <= end; n += 4) {
        float v0 = in[(size_t)(n+0)*HH + f];
        float v1 = in[(size_t)(n+1)*HH + f];
        float v2 = in[(size_t)(n+2)*HH + f];
        float v3 = in[(size_t)(n+3)*HH + f];
        mx = fmaxf(mx, fmaxf(fmaxf(v0, v1), fmaxf(v2, v3)));
        sm += v0 + v1 + v2 + v3;
    }
    for (; n < end; n++) {
        float v = in[(size_t)n*HH + f];
        mx = fmaxf(mx, v); sm += v;
    }
    xp[g*2*HH + f] = mx;
    xp[g*2*HH + HH + f] = sm / cnt;
}

// ---------------- small SIMT GEMM for the classifier ----------------
__global__ void __launch_bounds__(256)
k_gemm(const float* __restrict__ A, const float* __restrict__ W,
       float* __restrict__ C, int M, int Ncols, int Kd,
       const float* __restrict__ bias, int flags) {
    __shared__ float As[16][64];
    __shared__ float Bs[16][64];
    int tid = threadIdx.x;
    int m0 = blockIdx.y * 64, n0 = blockIdx.x * 64;
    int ty = tid >> 4, tx = tid & 15;
    int lm = tid >> 2;
    int lk = (tid & 3) * 4;
    int lkb = tid >> 4;
    int lnb = (tid & 15) * 4;

    float acc[4][4];
#pragma unroll
    for (int i = 0; i < 4; i++)
#pragma unroll
        for (int j = 0; j < 4; j++) acc[i][j] = 0.0f;

    for (int k0 = 0; k0 < Kd; k0 += 16) {
        float4 av = *(const float4*)(A + (size_t)(m0 + lm) * Kd + k0 + lk);
        As[lk+0][lm] = av.x; As[lk+1][lm] = av.y;
        As[lk+2][lm] = av.z; As[lk+3][lm] = av.w;
        float4 bv = *(const float4*)(W + (size_t)(k0 + lkb) * Ncols + n0 + lnb);
        *(float4*)&Bs[lkb][lnb] = bv;
        __syncthreads();
#pragma unroll
        for (int k = 0; k < 16; k++) {
            float4 a4 = *(const float4*)&As[k][ty*4];
            float4 b4 = *(const float4*)&Bs[k][tx*4];
            float ar[4] = {a4.x, a4.y, a4.z, a4.w};
            float br[4] = {b4.x, b4.y, b4.z, b4.w};
#pragma unroll
            for (int i = 0; i < 4; i++)
#pragma unroll
                for (int j = 0; j < 4; j++) acc[i][j] += ar[i] * br[j];
        }
        __syncthreads();
    }
#pragma unroll
    for (int i = 0; i < 4; i++) {
        int r = m0 + ty*4 + i;
#pragma unroll
        for (int j = 0; j < 4; j++) {
            int c = n0 + tx*4 + j;
            float v = acc[i][j];
            if (bias) v += bias[c];
            size_t o = (size_t)r * Ncols + c;
            if (flags & 1) v += C[o];
            if (flags & 2) v = fmaxf(v, 0.0f);
            if (flags & 4) v = gelu_exact(v);
            C[o] = v;
        }
    }
}

// ---------------- classifier tail ----------------
__global__ void k_final(const float* __restrict__ z1, const float* __restrict__ w2,
                        const float* __restrict__ b2, float* __restrict__ out) {
    int g = blockIdx.x * blockDim.x + threadIdx.x;
    if (g >= GG) return;
    float d0 = b2[0], d1 = b2[1];
    const float* zr = z1 + (size_t)g * HH;
#pragma unroll 4
    for (int j = 0; j < HH; j++) {
        float v = zr[j];
        d0 += v * w2[j*2 + 0];
        d1 += v * w2[j*2 + 1];
    }
    float mx = fmaxf(d0, d1);
    float l = logf(expf(d0 - mx) + expf(d1 - mx));
    out[g*2 + 0] = d0 - mx - l;
    out[g*2 + 1] = d1 - mx - l;
}

// ==========================================================================
extern "C" void kernel_launch(void* const* d_in, const int* in_sizes, int n_in,
                              void* d_out, int out_size) {
    __nv_bfloat16 *HA, *LA, *HB, *LB, *HC, *LC, *HD, *LD, *Whi, *Wlo;
    float *F, *asrc, *adst, *dinv, *xp, *z1;
    int *degi, *rowptr, *fillc, *csr, *bsum;
    cudaGetSymbolAddress((void**)&HA, g_HA);
    cudaGetSymbolAddress((void**)&LA, g_LA);
    cudaGetSymbolAddress((void**)&HB, g_HB);
    cudaGetSymbolAddress((void**)&LB, g_LB);
    cudaGetSymbolAddress((void**)&HC, g_HC);
    cudaGetSymbolAddress((void**)&LC, g_LC);
    cudaGetSymbolAddress((void**)&HD, g_HD);
    cudaGetSymbolAddress((void**)&LD, g_LD);
    cudaGetSymbolAddress((void**)&F, g_F);
    cudaGetSymbolAddress((void**)&asrc, g_asrc);
    cudaGetSymbolAddress((void**)&adst, g_adst);
    cudaGetSymbolAddress((void**)&dinv, g_dinv);
    cudaGetSymbolAddress((void**)&degi, g_degi);
    cudaGetSymbolAddress((void**)&rowptr, g_rowptr);
    cudaGetSymbolAddress((void**)&fillc, g_fillc);
    cudaGetSymbolAddress((void**)&csr, g_csr);
    cudaGetSymbolAddress((void**)&bsum, g_bsum);
    cudaGetSymbolAddress((void**)&xp, g_xp);
    cudaGetSymbolAddress((void**)&z1, g_z1);
    cudaGetSymbolAddress((void**)&Whi, g_Whi);
    cudaGetSymbolAddress((void**)&Wlo, g_Wlo);

    const float* x = (const float*)d_in[0];
    const int* ei = (const int*)d_in[1];
    int wb = n_in - 21;
    const float* enc_w   = (const float*)d_in[wb + 0];
    const float* enc_b   = (const float*)d_in[wb + 1];
    const float* gat_w   = (const float*)d_in[wb + 2];
    const float* att_src = (const float*)d_in[wb + 3];
    const float* att_dst = (const float*)d_in[wb + 4];
    const float* gat_b   = (const float*)d_in[wb + 5];
    const float* n1_w    = (const float*)d_in[wb + 6];
    const float* n1_b    = (const float*)d_in[wb + 7];
    const float* n1_ms   = (const float*)d_in[wb + 8];
    const float* tag_ws  = (const float*)d_in[wb + 9];
    const float* tag_b   = (const float*)d_in[wb + 10];
    const float* n2_w    = (const float*)d_in[wb + 11];
    const float* n2_b    = (const float*)d_in[wb + 12];
    const float* n2_ms   = (const float*)d_in[wb + 13];
    const float* gc_w_rel  = (const float*)d_in[wb + 14];
    const float* gc_b_rel  = (const float*)d_in[wb + 15];
    const float* gc_w_root = (const float*)d_in[wb + 16];
    const float* cls_w1  = (const float*)d_in[wb + 17];
    const float* cls_b1  = (const float*)d_in[wb + 18];
    const float* cls_w2  = (const float*)d_in[wb + 19];
    const float* cls_b2  = (const float*)d_in[wb + 20];

    static int init_done = 0;
    static cudaStream_t s1;
    static cudaEvent_t e_fork, e_join;
    if (!init_done) {
        cudaFuncSetAttribute(k_gemm_mma, cudaFuncAttributeMaxDynamicSharedMemorySize, SMTOT);
        cudaStreamCreateWithFlags(&s1, cudaStreamNonBlocking);
        cudaEventCreateWithFlags(&e_fork, cudaEventDisableTiming);
        cudaEventCreateWithFlags(&e_join, cudaEventDisableTiming);
        init_done = 1;
    }

    const int GT = (NN + 127) / 128;
    const dim3 gGemm(2, GT);               // x = N-half (fast), y = M-tile
    const int NBLK = (NN + 1023) / 1024;
    const int WGRID = (NN*32 + 255) / 256;
    dim3 gCls(HH / 64, GG / 64);

    // ---- fork: CSR build on s1, concurrent with weights/encoder/GEMM ----
    cudaEventRecord(e_fork, 0);
    cudaStreamWaitEvent(s1, e_fork, 0);

    cudaMemsetAsync(degi, 0, NN*sizeof(int), s1);
    cudaMemsetAsync(fillc, 0, NN*sizeof(int), s1);
    k_degi<<<(EE + 255)/256, 256, 0, s1>>>(ei, degi);
    k_scan1<<<NBLK, 256, 0, s1>>>(degi, bsum);
    k_scan2<<<1, 32, 0, s1>>>(bsum, rowptr, NBLK);
    k_scan3<<<NBLK, 256, 0, s1>>>(degi, bsum, rowptr);
    k_csrfill<<<(EE + 255)/256, 256, 0, s1>>>(ei, rowptr, fillc, csr);
    k_dinv2<<<(NN + 255)/256, 256, 0, s1>>>(degi, dinv);
    cudaEventRecord(e_join, s1);

    // main: weights + encoder + GAT GEMM + attention scores
    k_wsplit7<<<dim3(256, 7), 256>>>(gat_w, tag_ws, gc_w_rel, gc_w_root, Whi, Wlo);
    k_encoder<<<(NN*HH + 255)/256, 256>>>(x, enc_w, enc_b, HA, LA);
    k_gemm_mma<<<gGemm, 256, SMTOT>>>(HA, LA, HA, LA, HA, LA, HA, LA,
                                      Whi, Wlo, 0,0,0,0, 1,
                                      nullptr, HB, LB, nullptr, 0);       // hh
    k_attn<<<(NN*4 + 255)/256, 256>>>(HB, LB, att_src, att_dst, asrc, adst);

    cudaStreamWaitEvent(0, e_join, 0);

    // --- 2. GAT ---
    k_gat<<<WGRID, 256>>>(rowptr, csr, asrc, adst, HB, LB, F);
    k_gnorm<<<GG, 256>>>(F, HA, LA, gat_b, n1_w, n1_b, n1_ms);            // h1

    // --- 3. TAGConv K=3 (serial props, one fused 4-input GEMM) ---
    k_prop_csr<<<WGRID, 256>>>(rowptr, csr, dinv, HA, LA, HB, LB);        // hk1
    k_prop_csr<<<WGRID, 256>>>(rowptr, csr, dinv, HB, LB, HC, LC);        // hk2
    k_prop_csr<<<WGRID, 256>>>(rowptr, csr, dinv, HC, LC, HD, LD);        // hk3
    k_gemm_mma<<<gGemm, 256, SMTOT>>>(HA, LA, HB, LB, HC, LC, HD, LD,
                                      Whi, Wlo, 1,2,3,4, 4,
                                      F, nullptr, nullptr, nullptr, 0);
    k_gnorm<<<GG, 256>>>(F, HA, LA, tag_b, n2_w, n2_b, n2_ms);            // h2

    // --- 4. GraphConv (fused 2-input GEMM) ---
    k_prop_csr<<<WGRID, 256>>>(rowptr, csr, nullptr, HA, LA, HB, LB);     // agg
    k_gemm_mma<<<gGemm, 256, SMTOT>>>(HB, LB, HA, LA, HA, LA, HA, LA,
                                      Whi, Wlo, 5,6,0,0, 2,
                                      F, nullptr, nullptr, gc_b_rel, 1);

    // --- 5. pool + classifier ---
    k_pool<<<GG, 256>>>(F, xp);
    k_gemm<<<gCls, 256>>>(xp, cls_w1, z1, GG, HH, 2*HH, cls_b1, 4);
    k_final<<<(GG + 255)/256, 256>>>(z1, cls_w2, cls_b2, (float*)d_out);

    (void)in_sizes; (void)out_size;
}

// round 16
// speedup vs baseline: 1.0303x; 1.0303x over previous
#include <cuda_runtime.h>
#include <cuda_bf16.h>
#include <math.h>
#include <stdint.h>

#define NN 200000
#define EE 1600000
#define GG 1024
#define HH 256
#define FF 7

// ---------------- scratch (device globals, no allocation) ----------------
static __device__ __nv_bfloat16 g_HA[(size_t)NN*HH];
static __device__ __nv_bfloat16 g_LA[(size_t)NN*HH];
static __device__ __nv_bfloat16 g_HB[(size_t)NN*HH];
static __device__ __nv_bfloat16 g_LB[(size_t)NN*HH];
static __device__ __nv_bfloat16 g_HC[(size_t)NN*HH];
static __device__ __nv_bfloat16 g_LC[(size_t)NN*HH];
static __device__ __nv_bfloat16 g_HD[(size_t)NN*HH];
static __device__ __nv_bfloat16 g_LD[(size_t)NN*HH];
static __device__ float g_F[(size_t)NN*HH];
static __device__ float g_asrc[NN*4];
static __device__ float g_adst[NN*4];
static __device__ float g_dinv[NN];
static __device__ int   g_degi[NN];
static __device__ int   g_rowptr[NN+1];
static __device__ int   g_fillc[NN];
static __device__ int   g_csr[EE];
static __device__ int   g_bsum[256];
static __device__ float g_xp[GG*2*HH];
static __device__ float g_z1[GG*HH];
static __device__ __nv_bfloat16 g_Whi[7*65536];
static __device__ __nv_bfloat16 g_Wlo[7*65536];

__device__ __forceinline__ float gelu_exact(float v) {
    return 0.5f * v * (1.0f + erff(v * 0.7071067811865476f));
}

// ================= warp-MMA helpers (sm_80+ baseline PTX) =================
__device__ __forceinline__ uint32_t smem_u32(const void* p) {
    uint32_t a;
    asm("{ .reg .u64 t; cvta.to.shared.u64 t, %1; cvt.u32.u64 %0, t; }"
        : "=r"(a) : "l"(p));
    return a;
}
__device__ __forceinline__ void mma16816(float* c, const uint32_t* a, const uint32_t* b) {
    asm volatile("mma.sync.aligned.m16n8k16.row.col.f32.bf16.bf16.f32 "
        "{%0,%1,%2,%3}, {%4,%5,%6,%7}, {%8,%9}, {%0,%1,%2,%3};"
        : "+f"(c[0]), "+f"(c[1]), "+f"(c[2]), "+f"(c[3])
        : "r"(a[0]), "r"(a[1]), "r"(a[2]), "r"(a[3]), "r"(b[0]), "r"(b[1]));
}
__device__ __forceinline__ void ldm4(uint32_t* r, uint32_t addr) {
    asm volatile("ldmatrix.sync.aligned.m8n8.x4.shared.b16 {%0,%1,%2,%3}, [%4];"
        : "=r"(r[0]), "=r"(r[1]), "=r"(r[2]), "=r"(r[3]) : "r"(addr));
}
__device__ __forceinline__ void cpasync16(uint32_t dst, const void* src) {
    asm volatile("cp.async.cg.shared.global [%0], [%1], 16;" :: "r"(dst), "l"(src));
}
__device__ __forceinline__ void cpasync16z(uint32_t dst, const void* src, int n) {
    asm volatile("cp.async.cg.shared.global [%0], [%1], 16, %2;"
                 :: "r"(dst), "l"(src), "r"(n));
}
#define CP_COMMIT() asm volatile("cp.async.commit_group;" ::: "memory")
#define CP_WAIT1()  asm volatile("cp.async.wait_group 1;" ::: "memory")
#define CP_WAIT0()  asm volatile("cp.async.wait_group 0;" ::: "memory")

__device__ __forceinline__ uint32_t swz(int row, int kg) {
    return (uint32_t)(row * 64 + ((kg ^ ((row >> 1) & 3)) << 4));
}
__device__ __forceinline__ uint32_t pack_hilo(float a, float b, uint32_t& lo) {
    __nv_bfloat16 ha = __float2bfloat16_rn(a), hb = __float2bfloat16_rn(b);
    __nv_bfloat162 l2 = __floats2bfloat162_rn(a - __bfloat162float(ha),
                                              b - __bfloat162float(hb));
    __nv_bfloat162 h2(ha, hb);
    lo = *(uint32_t*)&l2;
    return *(uint32_t*)&h2;
}
__device__ __forceinline__ void unpack8(const uint4 H, const uint4 L, float* v) {
    const __nv_bfloat162* hp = (const __nv_bfloat162*)&H;
    const __nv_bfloat162* lp = (const __nv_bfloat162*)&L;
#pragma unroll
    for (int i = 0; i < 4; i++) {
        float2 a = __bfloat1622float2(hp[i]);
        float2 b = __bfloat1622float2(lp[i]);
        v[2*i]   = a.x + b.x;
        v[2*i+1] = a.y + b.y;
    }
}

// stage: AHI[0,8K) ALO[8K,16K) BHI[16K,24K) BLO[24K,32K); 3 stages
#define STG 32768
#define SMTOT (3*STG)

// ------------- weight transpose + bf16 hi/lo split (all 7 in one) --------
__global__ void k_wsplit7(const float* __restrict__ gat_w, const float* __restrict__ tag_ws,
                          const float* __restrict__ gc_w_rel, const float* __restrict__ gc_w_root,
                          __nv_bfloat16* __restrict__ hi, __nv_bfloat16* __restrict__ lo) {
    int slot = blockIdx.y;
    const float* W = (slot == 0) ? gat_w
                   : (slot <= 4) ? tag_ws + (size_t)(slot-1)*65536
                   : (slot == 5) ? gc_w_rel : gc_w_root;
    int idx = blockIdx.x * blockDim.x + threadIdx.x;
    if (idx >= 65536) return;
    int k = idx >> 8, n = idx & 255;
    float v = W[idx];
    __nv_bfloat16 h = __float2bfloat16_rn(v);
    float r = v - __bfloat162float(h);
    hi[(size_t)slot*65536 + n*256 + k] = h;
    lo[(size_t)slot*65536 + n*256 + k] = __float2bfloat16_rn(r);
}

// ---- tensor-core mega-GEMM, exact 3-product, 3-stage cp.async, 2 CTA/SM --
// Optional fused attention-score epilogue (GAT GEMM): asrc/adst written
// directly from register accumulators (each (row, head) owned by exactly
// one 4-lane group of one warp; reduce via shfl, no atomics).
__global__ void __launch_bounds__(256, 2)
k_gemm_mma(const __nv_bfloat16* H0, const __nv_bfloat16* L0,
           const __nv_bfloat16* H1, const __nv_bfloat16* L1,
           const __nv_bfloat16* H2, const __nv_bfloat16* L2,
           const __nv_bfloat16* H3, const __nv_bfloat16* L3,
           const __nv_bfloat16* __restrict__ Whi, const __nv_bfloat16* __restrict__ Wlo,
           int w0, int w1, int w2, int w3, int ninputs,
           float* outf, __nv_bfloat16* outh, __nv_bfloat16* outl,
           const float* bias, int relu,
           const float* att_src, const float* att_dst,
           float* asrc, float* adst) {
    extern __shared__ char sm[];
    uint32_t sb = smem_u32(sm);
    const int t = threadIdx.x;
    const int m0 = blockIdx.y * 128;
    const int n0 = blockIdx.x * 128;
    const __nv_bfloat16* His[4] = {H0, H1, H2, H3};
    const __nv_bfloat16* Lis[4] = {L0, L1, L2, L3};
    const int wof[4] = {w0, w1, w2, w3};
    const int CHN = ninputs * 8;

    const int r  = t >> 1;
    const int hf = t & 1;
    const int am = m0 + r;
    const int av = (am < NN) ? 16 : 0;
    const uint32_t s0 = swz(r, hf*2), s1 = swz(r, hf*2 + 1);

    float acc[2][8][4];
#pragma unroll
    for (int i = 0; i < 2; i++)
#pragma unroll
        for (int j = 0; j < 8; j++)
#pragma unroll
            for (int q = 0; q < 4; q++) acc[i][j][q] = 0.0f;

    auto issue = [&](int c, int stg) {
        int i = c >> 3, kc = c & 7;
        uint32_t base = sb + stg * STG;
        size_t aoff = (size_t)am * 256 + kc * 32 + hf * 16;
        size_t boff = (size_t)wof[i] * 65536 + (size_t)(n0 + r) * 256 + kc * 32 + hf * 16;
        cpasync16z(base + s0,         His[i] + aoff,     av);
        cpasync16z(base + s1,         His[i] + aoff + 8, av);
        cpasync16z(base + 8192 + s0,  Lis[i] + aoff,     av);
        cpasync16z(base + 8192 + s1,  Lis[i] + aoff + 8, av);
        cpasync16 (base + 16384 + s0, Whi + boff);
        cpasync16 (base + 16384 + s1, Whi + boff + 8);
        cpasync16 (base + 24576 + s0, Wlo + boff);
        cpasync16 (base + 24576 + s1, Wlo + boff + 8);
    };

    issue(0, 0); CP_COMMIT();
    if (CHN > 1) { issue(1, 1); CP_COMMIT(); }

    const int lane = t & 31, wid = t >> 5;
    const int wm = wid & 3, wn = wid >> 2;

    for (int c = 0; c < CHN; c++) {
        if (c + 1 < CHN) CP_WAIT1(); else CP_WAIT0();
        __syncthreads();
        if (c + 2 < CHN) { issue(c + 2, (c + 2) % 3); CP_COMMIT(); }

        uint32_t ab = sb + (c % 3) * STG;
        uint32_t alb = ab + 8192, bb = ab + 16384, blb = ab + 24576;
#pragma unroll
        for (int ks = 0; ks < 2; ks++) {
            uint32_t ah[2][4], al[2][4];
#pragma unroll
            for (int mf = 0; mf < 2; mf++) {
                int row = wm*32 + mf*16 + (lane & 15);
                int kg = ks*2 + (lane >> 4);
                ldm4(ah[mf], ab  + swz(row, kg));
                ldm4(al[mf], alb + swz(row, kg));
            }
#pragma unroll
            for (int nf2 = 0; nf2 < 4; nf2++) {
                int nrow = wn*64 + nf2*16 + (lane & 7) + ((lane >> 4) << 3);
                int kg = ks*2 + ((lane >> 3) & 1);
                uint32_t bh[4], bl[4];
                ldm4(bh, bb  + swz(nrow, kg));
                ldm4(bl, blb + swz(nrow, kg));
#pragma unroll
                for (int mf = 0; mf < 2; mf++) {
#pragma unroll
                    for (int h = 0; h < 2; h++) {
                        float* a = acc[mf][nf2*2 + h];
                        mma16816(a, ah[mf], bh + h*2);
                        mma16816(a, ah[mf], bl + h*2);
                        mma16816(a, al[mf], bh + h*2);
                    }
                }
            }
        }
    }

    const int mb = m0 + wm*32;
    const int nb = n0 + wn*64;
    const int head = nb >> 6;                 // this warp's N band = one head
    const float* ws = att_src ? att_src + head*64 : nullptr;
    const float* wd = att_dst ? att_dst + head*64 : nullptr;
#pragma unroll
    for (int mf = 0; mf < 2; mf++) {
        int r0 = mb + mf*16 + (lane >> 2);
        int r1 = r0 + 8;
        float as0 = 0.f, ad0 = 0.f, as1 = 0.f, ad1 = 0.f;
#pragma unroll
        for (int nf = 0; nf < 8; nf++) {
            int col = nb + nf*8 + (lane & 3)*2;
            float a0 = acc[mf][nf][0], a1 = acc[mf][nf][1];
            float a2 = acc[mf][nf][2], a3 = acc[mf][nf][3];
            if (outf) {
                float b0 = 0.f, b1 = 0.f;
                if (bias) { b0 = bias[col]; b1 = bias[col+1]; }
                float2 v0 = make_float2(a0 + b0, a1 + b1);
                float2 v1 = make_float2(a2 + b0, a3 + b1);
                if (relu) {
                    v0.x = fmaxf(v0.x, 0.f); v0.y = fmaxf(v0.y, 0.f);
                    v1.x = fmaxf(v1.x, 0.f); v1.y = fmaxf(v1.y, 0.f);
                }
                if (r0 < NN) *(float2*)(outf + (size_t)r0*256 + col) = v0;
                if (r1 < NN) *(float2*)(outf + (size_t)r1*256 + col) = v1;
            } else {
                uint32_t l0, l1;
                uint32_t h0 = pack_hilo(a0, a1, l0);
                uint32_t h1 = pack_hilo(a2, a3, l1);
                if (r0 < NN) {
                    *(uint32_t*)(outh + (size_t)r0*256 + col) = h0;
                    *(uint32_t*)(outl + (size_t)r0*256 + col) = l0;
                }
                if (r1 < NN) {
                    *(uint32_t*)(outh + (size_t)r1*256 + col) = h1;
                    *(uint32_t*)(outl + (size_t)r1*256 + col) = l1;
                }
                if (ws) {
                    int cb = nf*8 + (lane & 3)*2;
                    as0 += a0*ws[cb] + a1*ws[cb+1];
                    ad0 += a0*wd[cb] + a1*wd[cb+1];
                    as1 += a2*ws[cb] + a3*ws[cb+1];
                    ad1 += a2*wd[cb] + a3*wd[cb+1];
                }
            }
        }
        if (ws) {
            // reduce over the 4 lanes covering this row's 64-col head band
#pragma unroll
            for (int off = 1; off <= 2; off <<= 1) {
                as0 += __shfl_xor_sync(~0u, as0, off);
                ad0 += __shfl_xor_sync(~0u, ad0, off);
                as1 += __shfl_xor_sync(~0u, as1, off);
                ad1 += __shfl_xor_sync(~0u, ad1, off);
            }
            if ((lane & 3) == 0) {
                if (r0 < NN) { asrc[r0*4 + head] = as0; adst[r0*4 + head] = ad0; }
                if (r1 < NN) { asrc[r1*4 + head] = as1; adst[r1*4 + head] = ad1; }
            }
        }
    }
}

// ================= CSR construction (counting sort by dst) ================
__global__ void k_degi(const int* __restrict__ ei, int* __restrict__ degi) {
    int e = blockIdx.x * blockDim.x + threadIdx.x;
    if (e >= EE) return;
    atomicAdd(&degi[ei[EE + e]], 1);
}

__global__ void k_scan1(const int* __restrict__ degi, int* __restrict__ bsum) {
    __shared__ int s[256];
    int t = threadIdx.x, b = blockIdx.x;
    int base = b*1024 + t*4;
    int sum = 0;
#pragma unroll
    for (int k = 0; k < 4; k++) { int i = base + k; if (i < NN) sum += degi[i]; }
    s[t] = sum; __syncthreads();
    for (int off = 128; off > 0; off >>= 1) {
        if (t < off) s[t] += s[t+off];
        __syncthreads();
    }
    if (t == 0) bsum[b] = s[0];
}

__global__ void k_scan2(int* __restrict__ bsum, int* __restrict__ rowptr, int nblk) {
    if (threadIdx.x == 0 && blockIdx.x == 0) {
        int run = 0;
        for (int i = 0; i < nblk; i++) { int v = bsum[i]; bsum[i] = run; run += v; }
        rowptr[NN] = run;
    }
}

__global__ void k_scan3(const int* __restrict__ degi, const int* __restrict__ bsum,
                        int* __restrict__ rowptr) {
    __shared__ int s[256];
    int t = threadIdx.x, b = blockIdx.x;
    int base = b*1024 + t*4;
    int v[4]; int sum = 0;
#pragma unroll
    for (int k = 0; k < 4; k++) { int i = base + k; v[k] = (i < NN) ? degi[i] : 0; sum += v[k]; }
    s[t] = sum; __syncthreads();
    for (int off = 1; off < 256; off <<= 1) {
        int u = (t >= off) ? s[t-off] : 0;
        __syncthreads();
        s[t] += u;
        __syncthreads();
    }
    int run = bsum[b] + s[t] - sum;
#pragma unroll
    for (int k = 0; k < 4; k++) {
        int i = base + k;
        if (i < NN) rowptr[i] = run;
        run += v[k];
    }
}

__global__ void k_csrfill(const int* __restrict__ ei, const int* __restrict__ rowptr,
                          int* __restrict__ fillc, int* __restrict__ csr) {
    int e = blockIdx.x * blockDim.x + threadIdx.x;
    if (e >= EE) return;
    int r = ei[e], c = ei[EE + e];
    int pos = rowptr[c] + atomicAdd(&fillc[c], 1);
    csr[pos] = r;
}

__global__ void k_dinv2(const int* __restrict__ degi, float* __restrict__ dinv) {
    int i = blockIdx.x * blockDim.x + threadIdx.x;
    if (i >= NN) return;
    int d = degi[i];
    dinv[i] = d > 0 ? 1.0f / sqrtf((float)d) : 0.0f;
}

// ------------- encoder: h = gelu(x @ enc_w + enc_b) -> hi/lo -------------
__global__ void k_encoder(const float* __restrict__ x, const float* __restrict__ w,
                          const float* __restrict__ b,
                          __nv_bfloat16* __restrict__ Hd, __nv_bfloat16* __restrict__ Ld) {
    int idx = blockIdx.x * blockDim.x + threadIdx.x;
    if (idx >= NN * HH) return;
    int n = idx >> 8, j = idx & 255;
    float s = b[j];
#pragma unroll
    for (int f = 0; f < FF; f++) s += x[n*FF + f] * w[f*HH + j];
    float v = gelu_exact(s);
    __nv_bfloat16 h = __float2bfloat16_rn(v);
    Hd[idx] = h;
    Ld[idx] = __float2bfloat16_rn(v - __bfloat162float(h));
}

__device__ __forceinline__ float4 lrelu4(float4 v) {
    v.x = v.x > 0.f ? v.x : 0.2f*v.x;
    v.y = v.y > 0.f ? v.y : 0.2f*v.y;
    v.z = v.z > 0.f ? v.z : 0.2f*v.z;
    v.w = v.w > 0.f ? v.w : 0.2f*v.w;
    return v;
}

// ------- GAT: warp-per-dst softmax + weighted gather (hi/lo in, fp32 out) --
__global__ void __launch_bounds__(256)
k_gat(const int* __restrict__ rowptr, const int* __restrict__ csr,
      const float* __restrict__ asrc, const float* __restrict__ adst,
      const __nv_bfloat16* __restrict__ Hh, const __nv_bfloat16* __restrict__ Lh,
      float* __restrict__ out) {
    __shared__ int   s_sh[8][32];
    __shared__ float4 al_sh[8][32];
    int w = (blockIdx.x * blockDim.x + threadIdx.x) >> 5;
    if (w >= NN) return;
    int lane = threadIdx.x & 31;
    int wid = (threadIdx.x >> 5);
    int r0 = rowptr[w], deg = rowptr[w+1] - r0;
    int tot = deg + 1;
    float4 ad = *(const float4*)(adst + (size_t)w*4);
    int head = lane >> 3;
    float acc[8];
#pragma unroll
    for (int q = 0; q < 8; q++) acc[q] = 0.f;

    for (int base = 0; base < tot; base += 32) {
        int j = base + lane;
        int s = w;
        float4 al = make_float4(0.f, 0.f, 0.f, 0.f);
        bool valid = j < tot;
        float4 e = make_float4(-3.4e38f, -3.4e38f, -3.4e38f, -3.4e38f);
        if (valid) {
            if (j < deg) s = csr[r0 + j];
            float4 as = *(const float4*)(asrc + (size_t)s*4);
            e = lrelu4(make_float4(as.x+ad.x, as.y+ad.y, as.z+ad.z, as.w+ad.w));
        }
        float4 mx, den;
        if (tot <= 32) {
            mx = e;
#pragma unroll
            for (int off = 16; off > 0; off >>= 1) {
                mx.x = fmaxf(mx.x, __shfl_xor_sync(~0u, mx.x, off));
                mx.y = fmaxf(mx.y, __shfl_xor_sync(~0u, mx.y, off));
                mx.z = fmaxf(mx.z, __shfl_xor_sync(~0u, mx.z, off));
                mx.w = fmaxf(mx.w, __shfl_xor_sync(~0u, mx.w, off));
            }
            den = make_float4(valid ? expf(e.x - mx.x) : 0.f,
                              valid ? expf(e.y - mx.y) : 0.f,
                              valid ? expf(e.z - mx.z) : 0.f,
                              valid ? expf(e.w - mx.w) : 0.f);
            float4 ex = den;
#pragma unroll
            for (int off = 16; off > 0; off >>= 1) {
                den.x += __shfl_xor_sync(~0u, den.x, off);
                den.y += __shfl_xor_sync(~0u, den.y, off);
                den.z += __shfl_xor_sync(~0u, den.z, off);
                den.w += __shfl_xor_sync(~0u, den.w, off);
            }
            al = make_float4(ex.x/den.x, ex.y/den.y, ex.z/den.z, ex.w/den.w);
        } else {
            mx = make_float4(-3.4e38f, -3.4e38f, -3.4e38f, -3.4e38f);
            for (int jj = lane; jj < tot; jj += 32) {
                int ss = (jj < deg) ? csr[r0 + jj] : w;
                float4 as = *(const float4*)(asrc + (size_t)ss*4);
                float4 ee = lrelu4(make_float4(as.x+ad.x, as.y+ad.y, as.z+ad.z, as.w+ad.w));
                mx.x = fmaxf(mx.x, ee.x); mx.y = fmaxf(mx.y, ee.y);
                mx.z = fmaxf(mx.z, ee.z); mx.w = fmaxf(mx.w, ee.w);
            }
#pragma unroll
            for (int off = 16; off > 0; off >>= 1) {
                mx.x = fmaxf(mx.x, __shfl_xor_sync(~0u, mx.x, off));
                mx.y = fmaxf(mx.y, __shfl_xor_sync(~0u, mx.y, off));
                mx.z = fmaxf(mx.z, __shfl_xor_sync(~0u, mx.z, off));
                mx.w = fmaxf(mx.w, __shfl_xor_sync(~0u, mx.w, off));
            }
            den = make_float4(0.f, 0.f, 0.f, 0.f);
            for (int jj = lane; jj < tot; jj += 32) {
                int ss = (jj < deg) ? csr[r0 + jj] : w;
                float4 as = *(const float4*)(asrc + (size_t)ss*4);
                float4 ee = lrelu4(make_float4(as.x+ad.x, as.y+ad.y, as.z+ad.z, as.w+ad.w));
                den.x += expf(ee.x - mx.x); den.y += expf(ee.y - mx.y);
                den.z += expf(ee.z - mx.z); den.w += expf(ee.w - mx.w);
            }
#pragma unroll
            for (int off = 16; off > 0; off >>= 1) {
                den.x += __shfl_xor_sync(~0u, den.x, off);
                den.y += __shfl_xor_sync(~0u, den.y, off);
                den.z += __shfl_xor_sync(~0u, den.z, off);
                den.w += __shfl_xor_sync(~0u, den.w, off);
            }
            if (valid) {
                al.x = expf(e.x - mx.x) / den.x;
                al.y = expf(e.y - mx.y) / den.y;
                al.z = expf(e.z - mx.z) / den.z;
                al.w = expf(e.w - mx.w) / den.w;
            }
        }
        __syncwarp();
        s_sh[wid][lane] = s;
        al_sh[wid][lane] = al;
        __syncwarp();
        int cnt = min(32, tot - base);
        for (int i = 0; i < cnt; i++) {
            int ss = s_sh[wid][i];
            float aa = ((const float*)&al_sh[wid][i])[head];
            uint4 Hv = *(const uint4*)(Hh + (size_t)ss*256 + lane*8);
            uint4 Lv = *(const uint4*)(Lh + (size_t)ss*256 + lane*8);
            float v[8];
            unpack8(Hv, Lv, v);
#pragma unroll
            for (int q = 0; q < 8; q++) acc[q] += aa * v[q];
        }
    }
    float* op = out + (size_t)w*256 + lane*8;
    *(float4*)op       = make_float4(acc[0], acc[1], acc[2], acc[3]);
    *(float4*)(op + 4) = make_float4(acc[4], acc[5], acc[6], acc[7]);
}

// ------- CSR propagation (hi/lo in, hi/lo out) ----------------------------
__global__ void __launch_bounds__(256)
k_prop_csr(const int* __restrict__ rowptr, const int* __restrict__ csr,
           const float* __restrict__ dinv,
           const __nv_bfloat16* __restrict__ Hs, const __nv_bfloat16* __restrict__ Ls,
           __nv_bfloat16* __restrict__ Hd, __nv_bfloat16* __restrict__ Ld) {
    int c = (blockIdx.x * blockDim.x + threadIdx.x) >> 5;
    if (c >= NN) return;
    int lane = threadIdx.x & 31;
    int r0 = rowptr[c], deg = rowptr[c+1] - r0;
    float nc = dinv ? dinv[c] : 1.0f;
    float acc[8];
#pragma unroll
    for (int q = 0; q < 8; q++) acc[q] = 0.f;
    for (int base = 0; base < deg; base += 32) {
        int j = base + lane;
        int s = 0; float wt = 0.f;
        if (j < deg) {
            s = csr[r0 + j];
            wt = dinv ? dinv[s] * nc : 1.0f;
        }
        int cnt = min(32, deg - base);
        for (int i = 0; i < cnt; i++) {
            int ss = __shfl_sync(~0u, s, i);
            float ww = __shfl_sync(~0u, wt, i);
            uint4 Hv = *(const uint4*)(Hs + (size_t)ss*256 + lane*8);
            uint4 Lv = *(const uint4*)(Ls + (size_t)ss*256 + lane*8);
            float v[8];
            unpack8(Hv, Lv, v);
#pragma unroll
            for (int q = 0; q < 8; q++) acc[q] += ww * v[q];
        }
    }
    uint32_t l0, l1, l2, l3;
    uint32_t h0 = pack_hilo(acc[0], acc[1], l0);
    uint32_t h1 = pack_hilo(acc[2], acc[3], l1);
    uint32_t h2 = pack_hilo(acc[4], acc[5], l2);
    uint32_t h3 = pack_hilo(acc[6], acc[7], l3);
    *(uint4*)(Hd + (size_t)c*256 + lane*8) = make_uint4(h0, h1, h2, h3);
    *(uint4*)(Ld + (size_t)c*256 + lane*8) = make_uint4(l0, l1, l2, l3);
}

// ------- graph_norm (+prebias) + relu: fp32 in, hi/lo out ------------------
__global__ void __launch_bounds__(256)
k_gnorm(const float* __restrict__ in,
        __nv_bfloat16* __restrict__ Hd, __nv_bfloat16* __restrict__ Ld,
        const float* __restrict__ pb, const float* __restrict__ w,
        const float* __restrict__ b, const float* __restrict__ ms) {
    int g = blockIdx.x, f = threadIdx.x;
    int start = (g * NN + GG - 1) / GG;
    int end = ((g + 1) * NN + GG - 1) / GG;
    float cnt = (float)(end - start);
    float pbf = pb ? pb[f] : 0.0f;
    float s1 = 0.f, s2 = 0.f;
    int n = start;
    for (; n + 4 <= end; n += 4) {
        float y0 = in[(size_t)(n+0)*HH + f] + pbf;
        float y1 = in[(size_t)(n+1)*HH + f] + pbf;
        float y2 = in[(size_t)(n+2)*HH + f] + pbf;
        float y3 = in[(size_t)(n+3)*HH + f] + pbf;
        s1 += y0 + y1 + y2 + y3;
        s2 += y0*y0 + y1*y1 + y2*y2 + y3*y3;
    }
    for (; n < end; n++) {
        float y = in[(size_t)n*HH + f] + pbf;
        s1 += y; s2 += y*y;
    }
    float mu = s1 / cnt;
    float msf = ms[f];
    float var = s2 / cnt - msf * (2.0f - msf) * mu * mu;
    float scale = rsqrtf(var + 1e-5f) * w[f];
    float bf = b[f];
    float sub = msf * mu;
    for (n = start; n < end; n++) {
        float tt = (in[(size_t)n*HH + f] + pbf - sub) * scale + bf;
        tt = fmaxf(tt, 0.0f);
        __nv_bfloat16 h = __float2bfloat16_rn(tt);
        Hd[(size_t)n*HH + f] = h;
        Ld[(size_t)n*HH + f] = __float2bfloat16_rn(tt - __bfloat162float(h));
    }
}

// ---------------- pooling: [max | mean] per graph (fp32 in) ----------------
__global__ void __launch_bounds__(256)
k_pool(const float* __restrict__ in, float* __restrict__ xp) {
    int g = blockIdx.x, f = threadIdx.x;
    int start = (g * NN + GG - 1) / GG;
    int end = ((g + 1) * NN + GG - 1) / GG;
    float cnt = (float)(end - start);
    float mx = -3.4e38f, sm = 0.f;
    int n = start;
    for (; n + 4 <= end; n += 4) {
        float v0 = in[(size_t)(n+0)*HH + f];
        float v1 = in[(size_t)(n+1)*HH + f];
        float v2 = in[(size_t)(n+2)*HH + f];
        float v3 = in[(size_t)(n+3)*HH + f];
        mx = fmaxf(mx, fmaxf(fmaxf(v0, v1), fmaxf(v2, v3)));
        sm += v0 + v1 + v2 + v3;
    }
    for (; n < end; n++) {
        float v = in[(size_t)n*HH + f];
        mx = fmaxf(mx, v); sm += v;
    }
    xp[g*2*HH + f] = mx;
    xp[g*2*HH + HH + f] = sm / cnt;
}

// ---------------- small SIMT GEMM for the classifier ----------------
__global__ void __launch_bounds__(256)
k_gemm(const float* __restrict__ A, const float* __restrict__ W,
       float* __restrict__ C, int M, int Ncols, int Kd,
       const float* __restrict__ bias, int flags) {
    __shared__ float As[16][64];
    __shared__ float Bs[16][64];
    int tid = threadIdx.x;
    int m0 = blockIdx.y * 64, n0 = blockIdx.x * 64;
    int ty = tid >> 4, tx = tid & 15;
    int lm = tid >> 2;
    int lk = (tid & 3) * 4;
    int lkb = tid >> 4;
    int lnb = (tid & 15) * 4;

    float acc[4][4];
#pragma unroll
    for (int i = 0; i < 4; i++)
#pragma unroll
        for (int j = 0; j < 4; j++) acc[i][j] = 0.0f;

    for (int k0 = 0; k0 < Kd; k0 += 16) {
        float4 av = *(const float4*)(A + (size_t)(m0 + lm) * Kd + k0 + lk);
        As[lk+0][lm] = av.x; As[lk+1][lm] = av.y;
        As[lk+2][lm] = av.z; As[lk+3][lm] = av.w;
        float4 bv = *(const float4*)(W + (size_t)(k0 + lkb) * Ncols + n0 + lnb);
        *(float4*)&Bs[lkb][lnb] = bv;
        __syncthreads();
#pragma unroll
        for (int k = 0; k < 16; k++) {
            float4 a4 = *(const float4*)&As[k][ty*4];
            float4 b4 = *(const float4*)&Bs[k][tx*4];
            float ar[4] = {a4.x, a4.y, a4.z, a4.w};
            float br[4] = {b4.x, b4.y, b4.z, b4.w};
#pragma unroll
            for (int i = 0; i < 4; i++)
#pragma unroll
                for (int j = 0; j < 4; j++) acc[i][j] += ar[i] * br[j];
        }
        __syncthreads();
    }
#pragma unroll
    for (int i = 0; i < 4; i++) {
        int r = m0 + ty*4 + i;
#pragma unroll
        for (int j = 0; j < 4; j++) {
            int c = n0 + tx*4 + j;
            float v = acc[i][j];
            if (bias) v += bias[c];
            size_t o = (size_t)r * Ncols + c;
            if (flags & 1) v += C[o];
            if (flags & 2) v = fmaxf(v, 0.0f);
            if (flags & 4) v = gelu_exact(v);
            C[o] = v;
        }
    }
}

// ---------------- classifier tail ----------------
__global__ void k_final(const float* __restrict__ z1, const float* __restrict__ w2,
                        const float* __restrict__ b2, float* __restrict__ out) {
    int g = blockIdx.x * blockDim.x + threadIdx.x;
    if (g >= GG) return;
    float d0 = b2[0], d1 = b2[1];
    const float* zr = z1 + (size_t)g * HH;
#pragma unroll 4
    for (int j = 0; j < HH; j++) {
        float v = zr[j];
        d0 += v * w2[j*2 + 0];
        d1 += v * w2[j*2 + 1];
    }
    float mx = fmaxf(d0, d1);
    float l = logf(expf(d0 - mx) + expf(d1 - mx));
    out[g*2 + 0] = d0 - mx - l;
    out[g*2 + 1] = d1 - mx - l;
}

// ==========================================================================
extern "C" void kernel_launch(void* const* d_in, const int* in_sizes, int n_in,
                              void* d_out, int out_size) {
    __nv_bfloat16 *HA, *LA, *HB, *LB, *HC, *LC, *HD, *LD, *Whi, *Wlo;
    float *F, *asrc, *adst, *dinv, *xp, *z1;
    int *degi, *rowptr, *fillc, *csr, *bsum;
    cudaGetSymbolAddress((void**)&HA, g_HA);
    cudaGetSymbolAddress((void**)&LA, g_LA);
    cudaGetSymbolAddress((void**)&HB, g_HB);
    cudaGetSymbolAddress((void**)&LB, g_LB);
    cudaGetSymbolAddress((void**)&HC, g_HC);
    cudaGetSymbolAddress((void**)&LC, g_LC);
    cudaGetSymbolAddress((void**)&HD, g_HD);
    cudaGetSymbolAddress((void**)&LD, g_LD);
    cudaGetSymbolAddress((void**)&F, g_F);
    cudaGetSymbolAddress((void**)&asrc, g_asrc);
    cudaGetSymbolAddress((void**)&adst, g_adst);
    cudaGetSymbolAddress((void**)&dinv, g_dinv);
    cudaGetSymbolAddress((void**)&degi, g_degi);
    cudaGetSymbolAddress((void**)&rowptr, g_rowptr);
    cudaGetSymbolAddress((void**)&fillc, g_fillc);
    cudaGetSymbolAddress((void**)&csr, g_csr);
    cudaGetSymbolAddress((void**)&bsum, g_bsum);
    cudaGetSymbolAddress((void**)&xp, g_xp);
    cudaGetSymbolAddress((void**)&z1, g_z1);
    cudaGetSymbolAddress((void**)&Whi, g_Whi);
    cudaGetSymbolAddress((void**)&Wlo, g_Wlo);

    const float* x = (const float*)d_in[0];
    const int* ei = (const int*)d_in[1];
    int wb = n_in - 21;
    const float* enc_w   = (const float*)d_in[wb + 0];
    const float* enc_b   = (const float*)d_in[wb + 1];
    const float* gat_w   = (const float*)d_in[wb + 2];
    const float* att_src = (const float*)d_in[wb + 3];
    const float* att_dst = (const float*)d_in[wb + 4];
    const float* gat_b   = (const float*)d_in[wb + 5];
    const float* n1_w    = (const float*)d_in[wb + 6];
    const float* n1_b    = (const float*)d_in[wb + 7];
    const float* n1_ms   = (const float*)d_in[wb + 8];
    const float* tag_ws  = (const float*)d_in[wb + 9];
    const float* tag_b   = (const float*)d_in[wb + 10];
    const float* n2_w    = (const float*)d_in[wb + 11];
    const float* n2_b    = (const float*)d_in[wb + 12];
    const float* n2_ms   = (const float*)d_in[wb + 13];
    const float* gc_w_rel  = (const float*)d_in[wb + 14];
    const float* gc_b_rel  = (const float*)d_in[wb + 15];
    const float* gc_w_root = (const float*)d_in[wb + 16];
    const float* cls_w1  = (const float*)d_in[wb + 17];
    const float* cls_b1  = (const float*)d_in[wb + 18];
    const float* cls_w2  = (const float*)d_in[wb + 19];
    const float* cls_b2  = (const float*)d_in[wb + 20];

    static int init_done = 0;
    static cudaStream_t s1;
    static cudaEvent_t e_fork, e_join;
    if (!init_done) {
        cudaFuncSetAttribute(k_gemm_mma, cudaFuncAttributeMaxDynamicSharedMemorySize, SMTOT);
        cudaStreamCreateWithFlags(&s1, cudaStreamNonBlocking);
        cudaEventCreateWithFlags(&e_fork, cudaEventDisableTiming);
        cudaEventCreateWithFlags(&e_join, cudaEventDisableTiming);
        init_done = 1;
    }

    const int GT = (NN + 127) / 128;
    const dim3 gGemm(2, GT);
    const int NBLK = (NN + 1023) / 1024;
    const int WGRID = (NN*32 + 255) / 256;
    dim3 gCls(HH / 64, GG / 64);

    // ---- fork: CSR build on s1, concurrent with weights/encoder/GEMM ----
    cudaEventRecord(e_fork, 0);
    cudaStreamWaitEvent(s1, e_fork, 0);

    cudaMemsetAsync(degi, 0, NN*sizeof(int), s1);
    cudaMemsetAsync(fillc, 0, NN*sizeof(int), s1);
    k_degi<<<(EE + 255)/256, 256, 0, s1>>>(ei, degi);
    k_scan1<<<NBLK, 256, 0, s1>>>(degi, bsum);
    k_scan2<<<1, 32, 0, s1>>>(bsum, rowptr, NBLK);
    k_scan3<<<NBLK, 256, 0, s1>>>(degi, bsum, rowptr);
    k_csrfill<<<(EE + 255)/256, 256, 0, s1>>>(ei, rowptr, fillc, csr);
    k_dinv2<<<(NN + 255)/256, 256, 0, s1>>>(degi, dinv);
    cudaEventRecord(e_join, s1);

    // main: weights + encoder + GAT GEMM (fused attention-score epilogue)
    k_wsplit7<<<dim3(256, 7), 256>>>(gat_w, tag_ws, gc_w_rel, gc_w_root, Whi, Wlo);
    k_encoder<<<(NN*HH + 255)/256, 256>>>(x, enc_w, enc_b, HA, LA);
    k_gemm_mma<<<gGemm, 256, SMTOT>>>(HA, LA, HA, LA, HA, LA, HA, LA,
                                      Whi, Wlo, 0,0,0,0, 1,
                                      nullptr, HB, LB, nullptr, 0,
                                      att_src, att_dst, asrc, adst);      // hh + scores

    cudaStreamWaitEvent(0, e_join, 0);

    // --- 2. GAT ---
    k_gat<<<WGRID, 256>>>(rowptr, csr, asrc, adst, HB, LB, F);
    k_gnorm<<<GG, 256>>>(F, HA, LA, gat_b, n1_w, n1_b, n1_ms);            // h1

    // --- 3. TAGConv K=3 (serial props, one fused 4-input GEMM) ---
    k_prop_csr<<<WGRID, 256>>>(rowptr, csr, dinv, HA, LA, HB, LB);        // hk1
    k_prop_csr<<<WGRID, 256>>>(rowptr, csr, dinv, HB, LB, HC, LC);        // hk2
    k_prop_csr<<<WGRID, 256>>>(rowptr, csr, dinv, HC, LC, HD, LD);        // hk3
    k_gemm_mma<<<gGemm, 256, SMTOT>>>(HA, LA, HB, LB, HC, LC, HD, LD,
                                      Whi, Wlo, 1,2,3,4, 4,
                                      F, nullptr, nullptr, nullptr, 0,
                                      nullptr, nullptr, nullptr, nullptr);
    k_gnorm<<<GG, 256>>>(F, HA, LA, tag_b, n2_w, n2_b, n2_ms);            // h2

    // --- 4. GraphConv (fused 2-input GEMM) ---
    k_prop_csr<<<WGRID, 256>>>(rowptr, csr, nullptr, HA, LA, HB, LB);     // agg
    k_gemm_mma<<<gGemm, 256, SMTOT>>>(HB, LB, HA, LA, HA, LA, HA, LA,
                                      Whi, Wlo, 5,6,0,0, 2,
                                      F, nullptr, nullptr, gc_b_rel, 1,
                                      nullptr, nullptr, nullptr, nullptr);

    // --- 5. pool + classifier ---
    k_pool<<<GG, 256>>>(F, xp);
    k_gemm<<<gCls, 256>>>(xp, cls_w1, z1, GG, HH, 2*HH, cls_b1, 4);
    k_final<<<(GG + 255)/256, 256>>>(z1, cls_w2, cls_b2, (float*)d_out);

    (void)in_sizes; (void)out_size;
}

// round 17
// speedup vs baseline: 1.0333x; 1.0030x over previous
#include <cuda_runtime.h>
#include <cuda_bf16.h>
#include <math.h>
#include <stdint.h>

#define NN 200000
#define EE 1600000
#define GG 1024
#define HH 256
#define FF 7

// ---------------- scratch (device globals, no allocation) ----------------
static __device__ __nv_bfloat16 g_HA[(size_t)NN*HH];
static __device__ __nv_bfloat16 g_LA[(size_t)NN*HH];
static __device__ __nv_bfloat16 g_HB[(size_t)NN*HH];
static __device__ __nv_bfloat16 g_LB[(size_t)NN*HH];
static __device__ __nv_bfloat16 g_HC[(size_t)NN*HH];
static __device__ __nv_bfloat16 g_LC[(size_t)NN*HH];
static __device__ __nv_bfloat16 g_HD[(size_t)NN*HH];
static __device__ __nv_bfloat16 g_LD[(size_t)NN*HH];
static __device__ float g_F[(size_t)NN*HH];
static __device__ float g_asrc[NN*4];
static __device__ float g_adst[NN*4];
static __device__ float g_dinv[NN];
static __device__ int   g_degi[NN];
static __device__ int   g_rowptr[NN+1];
static __device__ int   g_fillc[NN];
static __device__ int   g_csr[EE];
static __device__ int   g_bsum[256];
static __device__ float g_xp[GG*2*HH];
static __device__ float g_z1[GG*HH];
static __device__ __nv_bfloat16 g_Whi[7*65536];
static __device__ __nv_bfloat16 g_Wlo[7*65536];

__device__ __forceinline__ float gelu_exact(float v) {
    return 0.5f * v * (1.0f + erff(v * 0.7071067811865476f));
}

// ================= warp-MMA helpers (sm_80+ baseline PTX) =================
__device__ __forceinline__ uint32_t smem_u32(const void* p) {
    uint32_t a;
    asm("{ .reg .u64 t; cvta.to.shared.u64 t, %1; cvt.u32.u64 %0, t; }"
        : "=r"(a) : "l"(p));
    return a;
}
__device__ __forceinline__ void mma16816(float* c, const uint32_t* a, const uint32_t* b) {
    asm volatile("mma.sync.aligned.m16n8k16.row.col.f32.bf16.bf16.f32 "
        "{%0,%1,%2,%3}, {%4,%5,%6,%7}, {%8,%9}, {%0,%1,%2,%3};"
        : "+f"(c[0]), "+f"(c[1]), "+f"(c[2]), "+f"(c[3])
        : "r"(a[0]), "r"(a[1]), "r"(a[2]), "r"(a[3]), "r"(b[0]), "r"(b[1]));
}
__device__ __forceinline__ void ldm4(uint32_t* r, uint32_t addr) {
    asm volatile("ldmatrix.sync.aligned.m8n8.x4.shared.b16 {%0,%1,%2,%3}, [%4];"
        : "=r"(r[0]), "=r"(r[1]), "=r"(r[2]), "=r"(r[3]) : "r"(addr));
}
__device__ __forceinline__ void cpasync16(uint32_t dst, const void* src) {
    asm volatile("cp.async.cg.shared.global [%0], [%1], 16;" :: "r"(dst), "l"(src));
}
__device__ __forceinline__ void cpasync16z(uint32_t dst, const void* src, int n) {
    asm volatile("cp.async.cg.shared.global [%0], [%1], 16, %2;"
                 :: "r"(dst), "l"(src), "r"(n));
}
#define CP_COMMIT() asm volatile("cp.async.commit_group;" ::: "memory")
#define CP_WAIT1()  asm volatile("cp.async.wait_group 1;" ::: "memory")
#define CP_WAIT0()  asm volatile("cp.async.wait_group 0;" ::: "memory")

__device__ __forceinline__ uint32_t swz(int row, int kg) {
    return (uint32_t)(row * 64 + ((kg ^ ((row >> 1) & 3)) << 4));
}
__device__ __forceinline__ uint32_t pack_hilo(float a, float b, uint32_t& lo) {
    __nv_bfloat16 ha = __float2bfloat16_rn(a), hb = __float2bfloat16_rn(b);
    __nv_bfloat162 l2 = __floats2bfloat162_rn(a - __bfloat162float(ha),
                                              b - __bfloat162float(hb));
    __nv_bfloat162 h2(ha, hb);
    lo = *(uint32_t*)&l2;
    return *(uint32_t*)&h2;
}
__device__ __forceinline__ void unpack8(const uint4 H, const uint4 L, float* v) {
    const __nv_bfloat162* hp = (const __nv_bfloat162*)&H;
    const __nv_bfloat162* lp = (const __nv_bfloat162*)&L;
#pragma unroll
    for (int i = 0; i < 4; i++) {
        float2 a = __bfloat1622float2(hp[i]);
        float2 b = __bfloat1622float2(lp[i]);
        v[2*i]   = a.x + b.x;
        v[2*i+1] = a.y + b.y;
    }
}

// stage: AHI[0,8K) ALO[8K,16K) BHI[16K,24K) BLO[24K,32K); 3 stages
#define STG 32768
#define SMTOT (3*STG)

// ------------- weight transpose + bf16 hi/lo split (all 7 in one) --------
__global__ void k_wsplit7(const float* __restrict__ gat_w, const float* __restrict__ tag_ws,
                          const float* __restrict__ gc_w_rel, const float* __restrict__ gc_w_root,
                          __nv_bfloat16* __restrict__ hi, __nv_bfloat16* __restrict__ lo) {
    int slot = blockIdx.y;
    const float* W = (slot == 0) ? gat_w
                   : (slot <= 4) ? tag_ws + (size_t)(slot-1)*65536
                   : (slot == 5) ? gc_w_rel : gc_w_root;
    int idx = blockIdx.x * blockDim.x + threadIdx.x;
    if (idx >= 65536) return;
    int k = idx >> 8, n = idx & 255;
    float v = W[idx];
    __nv_bfloat16 h = __float2bfloat16_rn(v);
    float r = v - __bfloat162float(h);
    hi[(size_t)slot*65536 + n*256 + k] = h;
    lo[(size_t)slot*65536 + n*256 + k] = __float2bfloat16_rn(r);
}

// ---- tensor-core mega-GEMM, exact 3-product, 3-stage cp.async, 2 CTA/SM --
// Epilogue modes: fp32 store | bf16 hi/lo store (+fused attn scores) |
// fused global max/sum pooling (bias+relu, atomics, no feature store).
__global__ void __launch_bounds__(256, 2)
k_gemm_mma(const __nv_bfloat16* H0, const __nv_bfloat16* L0,
           const __nv_bfloat16* H1, const __nv_bfloat16* L1,
           const __nv_bfloat16* H2, const __nv_bfloat16* L2,
           const __nv_bfloat16* H3, const __nv_bfloat16* L3,
           const __nv_bfloat16* __restrict__ Whi, const __nv_bfloat16* __restrict__ Wlo,
           int w0, int w1, int w2, int w3, int ninputs,
           float* outf, __nv_bfloat16* outh, __nv_bfloat16* outl,
           const float* bias, int relu,
           const float* att_src, const float* att_dst,
           float* asrc, float* adst,
           float* xp) {
    extern __shared__ char sm[];
    uint32_t sb = smem_u32(sm);
    const int t = threadIdx.x;
    const int m0 = blockIdx.y * 128;
    const int n0 = blockIdx.x * 128;
    const __nv_bfloat16* His[4] = {H0, H1, H2, H3};
    const __nv_bfloat16* Lis[4] = {L0, L1, L2, L3};
    const int wof[4] = {w0, w1, w2, w3};
    const int CHN = ninputs * 8;

    const int r  = t >> 1;
    const int hf = t & 1;
    const int am = m0 + r;
    const int av = (am < NN) ? 16 : 0;
    const uint32_t s0 = swz(r, hf*2), s1 = swz(r, hf*2 + 1);

    float acc[2][8][4];
#pragma unroll
    for (int i = 0; i < 2; i++)
#pragma unroll
        for (int j = 0; j < 8; j++)
#pragma unroll
            for (int q = 0; q < 4; q++) acc[i][j][q] = 0.0f;

    auto issue = [&](int c, int stg) {
        int i = c >> 3, kc = c & 7;
        uint32_t base = sb + stg * STG;
        size_t aoff = (size_t)am * 256 + kc * 32 + hf * 16;
        size_t boff = (size_t)wof[i] * 65536 + (size_t)(n0 + r) * 256 + kc * 32 + hf * 16;
        cpasync16z(base + s0,         His[i] + aoff,     av);
        cpasync16z(base + s1,         His[i] + aoff + 8, av);
        cpasync16z(base + 8192 + s0,  Lis[i] + aoff,     av);
        cpasync16z(base + 8192 + s1,  Lis[i] + aoff + 8, av);
        cpasync16 (base + 16384 + s0, Whi + boff);
        cpasync16 (base + 16384 + s1, Whi + boff + 8);
        cpasync16 (base + 24576 + s0, Wlo + boff);
        cpasync16 (base + 24576 + s1, Wlo + boff + 8);
    };

    issue(0, 0); CP_COMMIT();
    if (CHN > 1) { issue(1, 1); CP_COMMIT(); }

    const int lane = t & 31, wid = t >> 5;
    const int wm = wid & 3, wn = wid >> 2;

    for (int c = 0; c < CHN; c++) {
        if (c + 1 < CHN) CP_WAIT1(); else CP_WAIT0();
        __syncthreads();
        if (c + 2 < CHN) { issue(c + 2, (c + 2) % 3); CP_COMMIT(); }

        uint32_t ab = sb + (c % 3) * STG;
        uint32_t alb = ab + 8192, bb = ab + 16384, blb = ab + 24576;
#pragma unroll
        for (int ks = 0; ks < 2; ks++) {
            uint32_t ah[2][4], al[2][4];
#pragma unroll
            for (int mf = 0; mf < 2; mf++) {
                int row = wm*32 + mf*16 + (lane & 15);
                int kg = ks*2 + (lane >> 4);
                ldm4(ah[mf], ab  + swz(row, kg));
                ldm4(al[mf], alb + swz(row, kg));
            }
#pragma unroll
            for (int nf2 = 0; nf2 < 4; nf2++) {
                int nrow = wn*64 + nf2*16 + (lane & 7) + ((lane >> 4) << 3);
                int kg = ks*2 + ((lane >> 3) & 1);
                uint32_t bh[4], bl[4];
                ldm4(bh, bb  + swz(nrow, kg));
                ldm4(bl, blb + swz(nrow, kg));
#pragma unroll
                for (int mf = 0; mf < 2; mf++) {
#pragma unroll
                    for (int h = 0; h < 2; h++) {
                        float* a = acc[mf][nf2*2 + h];
                        mma16816(a, ah[mf], bh + h*2);
                        mma16816(a, ah[mf], bl + h*2);
                        mma16816(a, al[mf], bh + h*2);
                    }
                }
            }
        }
    }

    const int mb = m0 + wm*32;
    const int nb = n0 + wn*64;
    const int head = nb >> 6;
    const float* ws = att_src ? att_src + head*64 : nullptr;
    const float* wd = att_dst ? att_dst + head*64 : nullptr;
#pragma unroll
    for (int mf = 0; mf < 2; mf++) {
        int r0 = mb + mf*16 + (lane >> 2);
        int r1 = r0 + 8;
        float as0 = 0.f, ad0 = 0.f, as1 = 0.f, ad1 = 0.f;
        // pooling fast-path info for this 16-row window
        int wlo = mb + mf*16;
        long long gl = ((long long)wlo * GG) / NN;
        long long gh = ((long long)(wlo + 15) * GG) / NN;
        bool pfast = xp && (gl == gh) && (wlo + 15 < NN);
        int glo = (int)gl;
#pragma unroll
        for (int nf = 0; nf < 8; nf++) {
            int col = nb + nf*8 + (lane & 3)*2;
            float a0 = acc[mf][nf][0], a1 = acc[mf][nf][1];
            float a2 = acc[mf][nf][2], a3 = acc[mf][nf][3];
            if (xp) {
                float b0 = bias ? bias[col] : 0.f;
                float b1 = bias ? bias[col+1] : 0.f;
                float v00 = fmaxf(a0 + b0, 0.f), v01 = fmaxf(a1 + b1, 0.f);
                float v10 = fmaxf(a2 + b0, 0.f), v11 = fmaxf(a3 + b1, 0.f);
                if (pfast) {
                    float mA = fmaxf(v00, v10), mB = fmaxf(v01, v11);
                    float sA = v00 + v10,       sB = v01 + v11;
#pragma unroll
                    for (int off = 4; off <= 16; off <<= 1) {
                        mA = fmaxf(mA, __shfl_xor_sync(~0u, mA, off));
                        mB = fmaxf(mB, __shfl_xor_sync(~0u, mB, off));
                        sA += __shfl_xor_sync(~0u, sA, off);
                        sB += __shfl_xor_sync(~0u, sB, off);
                    }
                    if (lane < 4) {
                        float* pm = xp + (size_t)glo * 512;
                        atomicMax((int*)&pm[col],   __float_as_int(mA));
                        atomicMax((int*)&pm[col+1], __float_as_int(mB));
                        atomicAdd(&pm[256 + col],   sA);
                        atomicAdd(&pm[256 + col+1], sB);
                    }
                } else {
                    if (r0 < NN) {
                        int gg = (int)(((long long)r0 * GG) / NN);
                        float* pm = xp + (size_t)gg * 512;
                        atomicMax((int*)&pm[col],   __float_as_int(v00));
                        atomicMax((int*)&pm[col+1], __float_as_int(v01));
                        atomicAdd(&pm[256 + col],   v00);
                        atomicAdd(&pm[256 + col+1], v01);
                    }
                    if (r1 < NN) {
                        int gg = (int)(((long long)r1 * GG) / NN);
                        float* pm = xp + (size_t)gg * 512;
                        atomicMax((int*)&pm[col],   __float_as_int(v10));
                        atomicMax((int*)&pm[col+1], __float_as_int(v11));
                        atomicAdd(&pm[256 + col],   v10);
                        atomicAdd(&pm[256 + col+1], v11);
                    }
                }
            } else if (outf) {
                float b0 = 0.f, b1 = 0.f;
                if (bias) { b0 = bias[col]; b1 = bias[col+1]; }
                float2 v0 = make_float2(a0 + b0, a1 + b1);
                float2 v1 = make_float2(a2 + b0, a3 + b1);
                if (relu) {
                    v0.x = fmaxf(v0.x, 0.f); v0.y = fmaxf(v0.y, 0.f);
                    v1.x = fmaxf(v1.x, 0.f); v1.y = fmaxf(v1.y, 0.f);
                }
                if (r0 < NN) *(float2*)(outf + (size_t)r0*256 + col) = v0;
                if (r1 < NN) *(float2*)(outf + (size_t)r1*256 + col) = v1;
            } else {
                uint32_t l0, l1;
                uint32_t h0 = pack_hilo(a0, a1, l0);
                uint32_t h1 = pack_hilo(a2, a3, l1);
                if (r0 < NN) {
                    *(uint32_t*)(outh + (size_t)r0*256 + col) = h0;
                    *(uint32_t*)(outl + (size_t)r0*256 + col) = l0;
                }
                if (r1 < NN) {
                    *(uint32_t*)(outh + (size_t)r1*256 + col) = h1;
                    *(uint32_t*)(outl + (size_t)r1*256 + col) = l1;
                }
                if (ws) {
                    int cb = nf*8 + (lane & 3)*2;
                    as0 += a0*ws[cb] + a1*ws[cb+1];
                    ad0 += a0*wd[cb] + a1*wd[cb+1];
                    as1 += a2*ws[cb] + a3*ws[cb+1];
                    ad1 += a2*wd[cb] + a3*wd[cb+1];
                }
            }
        }
        if (!xp && !outf && ws) {
#pragma unroll
            for (int off = 1; off <= 2; off <<= 1) {
                as0 += __shfl_xor_sync(~0u, as0, off);
                ad0 += __shfl_xor_sync(~0u, ad0, off);
                as1 += __shfl_xor_sync(~0u, as1, off);
                ad1 += __shfl_xor_sync(~0u, ad1, off);
            }
            if ((lane & 3) == 0) {
                if (r0 < NN) { asrc[r0*4 + head] = as0; adst[r0*4 + head] = ad0; }
                if (r1 < NN) { asrc[r1*4 + head] = as1; adst[r1*4 + head] = ad1; }
            }
        }
    }
}

// ================= CSR construction (counting sort by dst) ================
__global__ void k_degi(const int* __restrict__ ei, int* __restrict__ degi) {
    int e = blockIdx.x * blockDim.x + threadIdx.x;
    if (e >= EE) return;
    atomicAdd(&degi[ei[EE + e]], 1);
}

__global__ void k_scan1(const int* __restrict__ degi, int* __restrict__ bsum) {
    __shared__ int s[256];
    int t = threadIdx.x, b = blockIdx.x;
    int base = b*1024 + t*4;
    int sum = 0;
#pragma unroll
    for (int k = 0; k < 4; k++) { int i = base + k; if (i < NN) sum += degi[i]; }
    s[t] = sum; __syncthreads();
    for (int off = 128; off > 0; off >>= 1) {
        if (t < off) s[t] += s[t+off];
        __syncthreads();
    }
    if (t == 0) bsum[b] = s[0];
}

__global__ void k_scan2(int* __restrict__ bsum, int* __restrict__ rowptr, int nblk) {
    if (threadIdx.x == 0 && blockIdx.x == 0) {
        int run = 0;
        for (int i = 0; i < nblk; i++) { int v = bsum[i]; bsum[i] = run; run += v; }
        rowptr[NN] = run;
    }
}

__global__ void k_scan3(const int* __restrict__ degi, const int* __restrict__ bsum,
                        int* __restrict__ rowptr) {
    __shared__ int s[256];
    int t = threadIdx.x, b = blockIdx.x;
    int base = b*1024 + t*4;
    int v[4]; int sum = 0;
#pragma unroll
    for (int k = 0; k < 4; k++) { int i = base + k; v[k] = (i < NN) ? degi[i] : 0; sum += v[k]; }
    s[t] = sum; __syncthreads();
    for (int off = 1; off < 256; off <<= 1) {
        int u = (t >= off) ? s[t-off] : 0;
        __syncthreads();
        s[t] += u;
        __syncthreads();
    }
    int run = bsum[b] + s[t] - sum;
#pragma unroll
    for (int k = 0; k < 4; k++) {
        int i = base + k;
        if (i < NN) rowptr[i] = run;
        run += v[k];
    }
}

__global__ void k_csrfill(const int* __restrict__ ei, const int* __restrict__ rowptr,
                          int* __restrict__ fillc, int* __restrict__ csr) {
    int e = blockIdx.x * blockDim.x + threadIdx.x;
    if (e >= EE) return;
    int r = ei[e], c = ei[EE + e];
    int pos = rowptr[c] + atomicAdd(&fillc[c], 1);
    csr[pos] = r;
}

__global__ void k_dinv2(const int* __restrict__ degi, float* __restrict__ dinv) {
    int i = blockIdx.x * blockDim.x + threadIdx.x;
    if (i >= NN) return;
    int d = degi[i];
    dinv[i] = d > 0 ? 1.0f / sqrtf((float)d) : 0.0f;
}

// ------------- encoder: h = gelu(x @ enc_w + enc_b) -> hi/lo -------------
__global__ void k_encoder(const float* __restrict__ x, const float* __restrict__ w,
                          const float* __restrict__ b,
                          __nv_bfloat16* __restrict__ Hd, __nv_bfloat16* __restrict__ Ld) {
    int idx = blockIdx.x * blockDim.x + threadIdx.x;
    if (idx >= NN * HH) return;
    int n = idx >> 8, j = idx & 255;
    float s = b[j];
#pragma unroll
    for (int f = 0; f < FF; f++) s += x[n*FF + f] * w[f*HH + j];
    float v = gelu_exact(s);
    __nv_bfloat16 h = __float2bfloat16_rn(v);
    Hd[idx] = h;
    Ld[idx] = __float2bfloat16_rn(v - __bfloat162float(h));
}

__device__ __forceinline__ float4 lrelu4(float4 v) {
    v.x = v.x > 0.f ? v.x : 0.2f*v.x;
    v.y = v.y > 0.f ? v.y : 0.2f*v.y;
    v.z = v.z > 0.f ? v.z : 0.2f*v.z;
    v.w = v.w > 0.f ? v.w : 0.2f*v.w;
    return v;
}

// ------- GAT: warp-per-dst softmax + weighted gather (hi/lo in, fp32 out) --
__global__ void __launch_bounds__(256)
k_gat(const int* __restrict__ rowptr, const int* __restrict__ csr,
      const float* __restrict__ asrc, const float* __restrict__ adst,
      const __nv_bfloat16* __restrict__ Hh, const __nv_bfloat16* __restrict__ Lh,
      float* __restrict__ out) {
    __shared__ int   s_sh[8][32];
    __shared__ float4 al_sh[8][32];
    int w = (blockIdx.x * blockDim.x + threadIdx.x) >> 5;
    if (w >= NN) return;
    int lane = threadIdx.x & 31;
    int wid = (threadIdx.x >> 5);
    int r0 = rowptr[w], deg = rowptr[w+1] - r0;
    int tot = deg + 1;
    float4 ad = *(const float4*)(adst + (size_t)w*4);
    int head = lane >> 3;
    float acc[8];
#pragma unroll
    for (int q = 0; q < 8; q++) acc[q] = 0.f;

    for (int base = 0; base < tot; base += 32) {
        int j = base + lane;
        int s = w;
        float4 al = make_float4(0.f, 0.f, 0.f, 0.f);
        bool valid = j < tot;
        float4 e = make_float4(-3.4e38f, -3.4e38f, -3.4e38f, -3.4e38f);
        if (valid) {
            if (j < deg) s = csr[r0 + j];
            float4 as = *(const float4*)(asrc + (size_t)s*4);
            e = lrelu4(make_float4(as.x+ad.x, as.y+ad.y, as.z+ad.z, as.w+ad.w));
        }
        float4 mx, den;
        if (tot <= 32) {
            mx = e;
#pragma unroll
            for (int off = 16; off > 0; off >>= 1) {
                mx.x = fmaxf(mx.x, __shfl_xor_sync(~0u, mx.x, off));
                mx.y = fmaxf(mx.y, __shfl_xor_sync(~0u, mx.y, off));
                mx.z = fmaxf(mx.z, __shfl_xor_sync(~0u, mx.z, off));
                mx.w = fmaxf(mx.w, __shfl_xor_sync(~0u, mx.w, off));
            }
            den = make_float4(valid ? expf(e.x - mx.x) : 0.f,
                              valid ? expf(e.y - mx.y) : 0.f,
                              valid ? expf(e.z - mx.z) : 0.f,
                              valid ? expf(e.w - mx.w) : 0.f);
            float4 ex = den;
#pragma unroll
            for (int off = 16; off > 0; off >>= 1) {
                den.x += __shfl_xor_sync(~0u, den.x, off);
                den.y += __shfl_xor_sync(~0u, den.y, off);
                den.z += __shfl_xor_sync(~0u, den.z, off);
                den.w += __shfl_xor_sync(~0u, den.w, off);
            }
            al = make_float4(ex.x/den.x, ex.y/den.y, ex.z/den.z, ex.w/den.w);
        } else {
            mx = make_float4(-3.4e38f, -3.4e38f, -3.4e38f, -3.4e38f);
            for (int jj = lane; jj < tot; jj += 32) {
                int ss = (jj < deg) ? csr[r0 + jj] : w;
                float4 as = *(const float4*)(asrc + (size_t)ss*4);
                float4 ee = lrelu4(make_float4(as.x+ad.x, as.y+ad.y, as.z+ad.z, as.w+ad.w));
                mx.x = fmaxf(mx.x, ee.x); mx.y = fmaxf(mx.y, ee.y);
                mx.z = fmaxf(mx.z, ee.z); mx.w = fmaxf(mx.w, ee.w);
            }
#pragma unroll
            for (int off = 16; off > 0; off >>= 1) {
                mx.x = fmaxf(mx.x, __shfl_xor_sync(~0u, mx.x, off));
                mx.y = fmaxf(mx.y, __shfl_xor_sync(~0u, mx.y, off));
                mx.z = fmaxf(mx.z, __shfl_xor_sync(~0u, mx.z, off));
                mx.w = fmaxf(mx.w, __shfl_xor_sync(~0u, mx.w, off));
            }
            den = make_float4(0.f, 0.f, 0.f, 0.f);
            for (int jj = lane; jj < tot; jj += 32) {
                int ss = (jj < deg) ? csr[r0 + jj] : w;
                float4 as = *(const float4*)(asrc + (size_t)ss*4);
                float4 ee = lrelu4(make_float4(as.x+ad.x, as.y+ad.y, as.z+ad.z, as.w+ad.w));
                den.x += expf(ee.x - mx.x); den.y += expf(ee.y - mx.y);
                den.z += expf(ee.z - mx.z); den.w += expf(ee.w - mx.w);
            }
#pragma unroll
            for (int off = 16; off > 0; off >>= 1) {
                den.x += __shfl_xor_sync(~0u, den.x, off);
                den.y += __shfl_xor_sync(~0u, den.y, off);
                den.z += __shfl_xor_sync(~0u, den.z, off);
                den.w += __shfl_xor_sync(~0u, den.w, off);
            }
            if (valid) {
                al.x = expf(e.x - mx.x) / den.x;
                al.y = expf(e.y - mx.y) / den.y;
                al.z = expf(e.z - mx.z) / den.z;
                al.w = expf(e.w - mx.w) / den.w;
            }
        }
        __syncwarp();
        s_sh[wid][lane] = s;
        al_sh[wid][lane] = al;
        __syncwarp();
        int cnt = min(32, tot - base);
        for (int i = 0; i < cnt; i++) {
            int ss = s_sh[wid][i];
            float aa = ((const float*)&al_sh[wid][i])[head];
            uint4 Hv = *(const uint4*)(Hh + (size_t)ss*256 + lane*8);
            uint4 Lv = *(const uint4*)(Lh + (size_t)ss*256 + lane*8);
            float v[8];
            unpack8(Hv, Lv, v);
#pragma unroll
            for (int q = 0; q < 8; q++) acc[q] += aa * v[q];
        }
    }
    float* op = out + (size_t)w*256 + lane*8;
    *(float4*)op       = make_float4(acc[0], acc[1], acc[2], acc[3]);
    *(float4*)(op + 4) = make_float4(acc[4], acc[5], acc[6], acc[7]);
}

// ------- CSR propagation (hi/lo in, hi/lo out) ----------------------------
__global__ void __launch_bounds__(256)
k_prop_csr(const int* __restrict__ rowptr, const int* __restrict__ csr,
           const float* __restrict__ dinv,
           const __nv_bfloat16* __restrict__ Hs, const __nv_bfloat16* __restrict__ Ls,
           __nv_bfloat16* __restrict__ Hd, __nv_bfloat16* __restrict__ Ld) {
    int c = (blockIdx.x * blockDim.x + threadIdx.x) >> 5;
    if (c >= NN) return;
    int lane = threadIdx.x & 31;
    int r0 = rowptr[c], deg = rowptr[c+1] - r0;
    float nc = dinv ? dinv[c] : 1.0f;
    float acc[8];
#pragma unroll
    for (int q = 0; q < 8; q++) acc[q] = 0.f;
    for (int base = 0; base < deg; base += 32) {
        int j = base + lane;
        int s = 0; float wt = 0.f;
        if (j < deg) {
            s = csr[r0 + j];
            wt = dinv ? dinv[s] * nc : 1.0f;
        }
        int cnt = min(32, deg - base);
        for (int i = 0; i < cnt; i++) {
            int ss = __shfl_sync(~0u, s, i);
            float ww = __shfl_sync(~0u, wt, i);
            uint4 Hv = *(const uint4*)(Hs + (size_t)ss*256 + lane*8);
            uint4 Lv = *(const uint4*)(Ls + (size_t)ss*256 + lane*8);
            float v[8];
            unpack8(Hv, Lv, v);
#pragma unroll
            for (int q = 0; q < 8; q++) acc[q] += ww * v[q];
        }
    }
    uint32_t l0, l1, l2, l3;
    uint32_t h0 = pack_hilo(acc[0], acc[1], l0);
    uint32_t h1 = pack_hilo(acc[2], acc[3], l1);
    uint32_t h2 = pack_hilo(acc[4], acc[5], l2);
    uint32_t h3 = pack_hilo(acc[6], acc[7], l3);
    *(uint4*)(Hd + (size_t)c*256 + lane*8) = make_uint4(h0, h1, h2, h3);
    *(uint4*)(Ld + (size_t)c*256 + lane*8) = make_uint4(l0, l1, l2, l3);
}

// ------- graph_norm (+prebias) + relu: fp32 in, hi/lo out ------------------
__global__ void __launch_bounds__(256)
k_gnorm(const float* __restrict__ in,
        __nv_bfloat16* __restrict__ Hd, __nv_bfloat16* __restrict__ Ld,
        const float* __restrict__ pb, const float* __restrict__ w,
        const float* __restrict__ b, const float* __restrict__ ms) {
    int g = blockIdx.x, f = threadIdx.x;
    int start = (g * NN + GG - 1) / GG;
    int end = ((g + 1) * NN + GG - 1) / GG;
    float cnt = (float)(end - start);
    float pbf = pb ? pb[f] : 0.0f;
    float s1 = 0.f, s2 = 0.f;
    int n = start;
    for (; n + 4 <= end; n += 4) {
        float y0 = in[(size_t)(n+0)*HH + f] + pbf;
        float y1 = in[(size_t)(n+1)*HH + f] + pbf;
        float y2 = in[(size_t)(n+2)*HH + f] + pbf;
        float y3 = in[(size_t)(n+3)*HH + f] + pbf;
        s1 += y0 + y1 + y2 + y3;
        s2 += y0*y0 + y1*y1 + y2*y2 + y3*y3;
    }
    for (; n < end; n++) {
        float y = in[(size_t)n*HH + f] + pbf;
        s1 += y; s2 += y*y;
    }
    float mu = s1 / cnt;
    float msf = ms[f];
    float var = s2 / cnt - msf * (2.0f - msf) * mu * mu;
    float scale = rsqrtf(var + 1e-5f) * w[f];
    float bf = b[f];
    float sub = msf * mu;
    for (n = start; n < end; n++) {
        float tt = (in[(size_t)n*HH + f] + pbf - sub) * scale + bf;
        tt = fmaxf(tt, 0.0f);
        __nv_bfloat16 h = __float2bfloat16_rn(tt);
        Hd[(size_t)n*HH + f] = h;
        Ld[(size_t)n*HH + f] = __float2bfloat16_rn(tt - __bfloat162float(h));
    }
}

// ------- mean fixup: xp[g][256+f] /= count(g) ------------------------------
__global__ void k_fixmean(float* __restrict__ xp) {
    int idx = blockIdx.x * blockDim.x + threadIdx.x;
    if (idx >= GG * HH) return;
    int g = idx >> 8, f = idx & 255;
    int start = (g * NN + GG - 1) / GG;
    int end = ((g + 1) * NN + GG - 1) / GG;
    xp[(size_t)g * 512 + 256 + f] /= (float)(end - start);
}

// ---------------- small SIMT GEMM for the classifier ----------------
__global__ void __launch_bounds__(256)
k_gemm(const float* __restrict__ A, const float* __restrict__ W,
       float* __restrict__ C, int M, int Ncols, int Kd,
       const float* __restrict__ bias, int flags) {
    __shared__ float As[16][64];
    __shared__ float Bs[16][64];
    int tid = threadIdx.x;
    int m0 = blockIdx.y * 64, n0 = blockIdx.x * 64;
    int ty = tid >> 4, tx = tid & 15;
    int lm = tid >> 2;
    int lk = (tid & 3) * 4;
    int lkb = tid >> 4;
    int lnb = (tid & 15) * 4;

    float acc[4][4];
#pragma unroll
    for (int i = 0; i < 4; i++)
#pragma unroll
        for (int j = 0; j < 4; j++) acc[i][j] = 0.0f;

    for (int k0 = 0; k0 < Kd; k0 += 16) {
        float4 av = *(const float4*)(A + (size_t)(m0 + lm) * Kd + k0 + lk);
        As[lk+0][lm] = av.x; As[lk+1][lm] = av.y;
        As[lk+2][lm] = av.z; As[lk+3][lm] = av.w;
        float4 bv = *(const float4*)(W + (size_t)(k0 + lkb) * Ncols + n0 + lnb);
        *(float4*)&Bs[lkb][lnb] = bv;
        __syncthreads();
#pragma unroll
        for (int k = 0; k < 16; k++) {
            float4 a4 = *(const float4*)&As[k][ty*4];
            float4 b4 = *(const float4*)&Bs[k][tx*4];
            float ar[4] = {a4.x, a4.y, a4.z, a4.w};
            float br[4] = {b4.x, b4.y, b4.z, b4.w};
#pragma unroll
            for (int i = 0; i < 4; i++)
#pragma unroll
                for (int j = 0; j < 4; j++) acc[i][j] += ar[i] * br[j];
        }
        __syncthreads();
    }
#pragma unroll
    for (int i = 0; i < 4; i++) {
        int r = m0 + ty*4 + i;
#pragma unroll
        for (int j = 0; j < 4; j++) {
            int c = n0 + tx*4 + j;
            float v = acc[i][j];
            if (bias) v += bias[c];
            size_t o = (size_t)r * Ncols + c;
            if (flags & 1) v += C[o];
            if (flags & 2) v = fmaxf(v, 0.0f);
            if (flags & 4) v = gelu_exact(v);
            C[o] = v;
        }
    }
}

// ---------------- classifier tail ----------------
__global__ void k_final(const float* __restrict__ z1, const float* __restrict__ w2,
                        const float* __restrict__ b2, float* __restrict__ out) {
    int g = blockIdx.x * blockDim.x + threadIdx.x;
    if (g >= GG) return;
    float d0 = b2[0], d1 = b2[1];
    const float* zr = z1 + (size_t)g * HH;
#pragma unroll 4
    for (int j = 0; j < HH; j++) {
        float v = zr[j];
        d0 += v * w2[j*2 + 0];
        d1 += v * w2[j*2 + 1];
    }
    float mx = fmaxf(d0, d1);
    float l = logf(expf(d0 - mx) + expf(d1 - mx));
    out[g*2 + 0] = d0 - mx - l;
    out[g*2 + 1] = d1 - mx - l;
}

// ==========================================================================
extern "C" void kernel_launch(void* const* d_in, const int* in_sizes, int n_in,
                              void* d_out, int out_size) {
    __nv_bfloat16 *HA, *LA, *HB, *LB, *HC, *LC, *HD, *LD, *Whi, *Wlo;
    float *F, *asrc, *adst, *dinv, *xp, *z1;
    int *degi, *rowptr, *fillc, *csr, *bsum;
    cudaGetSymbolAddress((void**)&HA, g_HA);
    cudaGetSymbolAddress((void**)&LA, g_LA);
    cudaGetSymbolAddress((void**)&HB, g_HB);
    cudaGetSymbolAddress((void**)&LB, g_LB);
    cudaGetSymbolAddress((void**)&HC, g_HC);
    cudaGetSymbolAddress((void**)&LC, g_LC);
    cudaGetSymbolAddress((void**)&HD, g_HD);
    cudaGetSymbolAddress((void**)&LD, g_LD);
    cudaGetSymbolAddress((void**)&F, g_F);
    cudaGetSymbolAddress((void**)&asrc, g_asrc);
    cudaGetSymbolAddress((void**)&adst, g_adst);
    cudaGetSymbolAddress((void**)&dinv, g_dinv);
    cudaGetSymbolAddress((void**)&degi, g_degi);
    cudaGetSymbolAddress((void**)&rowptr, g_rowptr);
    cudaGetSymbolAddress((void**)&fillc, g_fillc);
    cudaGetSymbolAddress((void**)&csr, g_csr);
    cudaGetSymbolAddress((void**)&bsum, g_bsum);
    cudaGetSymbolAddress((void**)&xp, g_xp);
    cudaGetSymbolAddress((void**)&z1, g_z1);
    cudaGetSymbolAddress((void**)&Whi, g_Whi);
    cudaGetSymbolAddress((void**)&Wlo, g_Wlo);

    const float* x = (const float*)d_in[0];
    const int* ei = (const int*)d_in[1];
    int wb = n_in - 21;
    const float* enc_w   = (const float*)d_in[wb + 0];
    const float* enc_b   = (const float*)d_in[wb + 1];
    const float* gat_w   = (const float*)d_in[wb + 2];
    const float* att_src = (const float*)d_in[wb + 3];
    const float* att_dst = (const float*)d_in[wb + 4];
    const float* gat_b   = (const float*)d_in[wb + 5];
    const float* n1_w    = (const float*)d_in[wb + 6];
    const float* n1_b    = (const float*)d_in[wb + 7];
    const float* n1_ms   = (const float*)d_in[wb + 8];
    const float* tag_ws  = (const float*)d_in[wb + 9];
    const float* tag_b   = (const float*)d_in[wb + 10];
    const float* n2_w    = (const float*)d_in[wb + 11];
    const float* n2_b    = (const float*)d_in[wb + 12];
    const float* n2_ms   = (const float*)d_in[wb + 13];
    const float* gc_w_rel  = (const float*)d_in[wb + 14];
    const float* gc_b_rel  = (const float*)d_in[wb + 15];
    const float* gc_w_root = (const float*)d_in[wb + 16];
    const float* cls_w1  = (const float*)d_in[wb + 17];
    const float* cls_b1  = (const float*)d_in[wb + 18];
    const float* cls_w2  = (const float*)d_in[wb + 19];
    const float* cls_b2  = (const float*)d_in[wb + 20];

    static int init_done = 0;
    static cudaStream_t s1;
    static cudaEvent_t e_fork, e_join;
    if (!init_done) {
        cudaFuncSetAttribute(k_gemm_mma, cudaFuncAttributeMaxDynamicSharedMemorySize, SMTOT);
        cudaStreamCreateWithFlags(&s1, cudaStreamNonBlocking);
        cudaEventCreateWithFlags(&e_fork, cudaEventDisableTiming);
        cudaEventCreateWithFlags(&e_join, cudaEventDisableTiming);
        init_done = 1;
    }

    const int GT = (NN + 127) / 128;
    const dim3 gGemm(2, GT);
    const int NBLK = (NN + 1023) / 1024;
    const int WGRID = (NN*32 + 255) / 256;
    dim3 gCls(HH / 64, GG / 64);

    // ---- fork: CSR build on s1, concurrent with weights/encoder/GEMM ----
    cudaEventRecord(e_fork, 0);
    cudaStreamWaitEvent(s1, e_fork, 0);

    cudaMemsetAsync(degi, 0, NN*sizeof(int), s1);
    cudaMemsetAsync(fillc, 0, NN*sizeof(int), s1);
    k_degi<<<(EE + 255)/256, 256, 0, s1>>>(ei, degi);
    k_scan1<<<NBLK, 256, 0, s1>>>(degi, bsum);
    k_scan2<<<1, 32, 0, s1>>>(bsum, rowptr, NBLK);
    k_scan3<<<NBLK, 256, 0, s1>>>(degi, bsum, rowptr);
    k_csrfill<<<(EE + 255)/256, 256, 0, s1>>>(ei, rowptr, fillc, csr);
    k_dinv2<<<(NN + 255)/256, 256, 0, s1>>>(degi, dinv);
    cudaEventRecord(e_join, s1);

    // main: pool-buffer clear + weights + encoder + GAT GEMM (fused scores)
    cudaMemsetAsync(xp, 0, (size_t)GG*2*HH*sizeof(float));
    k_wsplit7<<<dim3(256, 7), 256>>>(gat_w, tag_ws, gc_w_rel, gc_w_root, Whi, Wlo);
    k_encoder<<<(NN*HH + 255)/256, 256>>>(x, enc_w, enc_b, HA, LA);
    k_gemm_mma<<<gGemm, 256, SMTOT>>>(HA, LA, HA, LA, HA, LA, HA, LA,
                                      Whi, Wlo, 0,0,0,0, 1,
                                      nullptr, HB, LB, nullptr, 0,
                                      att_src, att_dst, asrc, adst, nullptr);

    cudaStreamWaitEvent(0, e_join, 0);

    // --- 2. GAT ---
    k_gat<<<WGRID, 256>>>(rowptr, csr, asrc, adst, HB, LB, F);
    k_gnorm<<<GG, 256>>>(F, HA, LA, gat_b, n1_w, n1_b, n1_ms);            // h1

    // --- 3. TAGConv K=3 (serial props, one fused 4-input GEMM) ---
    k_prop_csr<<<WGRID, 256>>>(rowptr, csr, dinv, HA, LA, HB, LB);        // hk1
    k_prop_csr<<<WGRID, 256>>>(rowptr, csr, dinv, HB, LB, HC, LC);        // hk2
    k_prop_csr<<<WGRID, 256>>>(rowptr, csr, dinv, HC, LC, HD, LD);        // hk3
    k_gemm_mma<<<gGemm, 256, SMTOT>>>(HA, LA, HB, LB, HC, LC, HD, LD,
                                      Whi, Wlo, 1,2,3,4, 4,
                                      F, nullptr, nullptr, nullptr, 0,
                                      nullptr, nullptr, nullptr, nullptr, nullptr);
    k_gnorm<<<GG, 256>>>(F, HA, LA, tag_b, n2_w, n2_b, n2_ms);            // h2

    // --- 4. GraphConv: fused 2-input GEMM + bias + relu + global pooling ---
    k_prop_csr<<<WGRID, 256>>>(rowptr, csr, nullptr, HA, LA, HB, LB);     // agg
    k_gemm_mma<<<gGemm, 256, SMTOT>>>(HB, LB, HA, LA, HA, LA, HA, LA,
                                      Whi, Wlo, 5,6,0,0, 2,
                                      nullptr, nullptr, nullptr, gc_b_rel, 1,
                                      nullptr, nullptr, nullptr, nullptr, xp);

    // --- 5. classifier (pool already fused) ---
    k_fixmean<<<(GG*HH + 255)/256, 256>>>(xp);
    k_gemm<<<gCls, 256>>>(xp, cls_w1, z1, GG, HH, 2*HH, cls_b1, 4);
    k_final<<<(GG + 255)/256, 256>>>(z1, cls_w2, cls_b2, (float*)d_out);

    (void)in_sizes; (void)out_size;
}